// round 1
// baseline (speedup 1.0000x reference)
#include <cuda_runtime.h>
#include <math.h>

// ---------------- problem dims ----------------
#define B_   1024
#define D_   1024
#define U_   2048
#define NB   4
#define M_   2048
#define MD_  1024
#define O_   512
#define KX   (D_*NB)   // 4096

// ---------------- device scratch (allocation-free) ----------------
__device__ float d_w2[KX * U_];        // 32 MB  w transposed to (i*4+n, u)
__device__ float d_xg[B_ * KX];        // 16 MB  x[b,i]*gate[b,n]
__device__ float d_gate[B_ * NB];
__device__ float d_hidden[B_ * U_];    // 8 MB (pre, then activated in place)
__device__ float d_att[B_ * M_];       // 8 MB (logits, then softmax in place)
__device__ float d_read[B_ * MD_];     // 4 MB
__device__ float d_cand[B_ * MD_];     // 4 MB
__device__ float d_preds[B_ * O_];     // 2 MB
__device__ float d_feat[B_ * 96];
__device__ float d_fused[B_ * 64];
__device__ float d_cma[M_];
__device__ float d_cmc[MD_];
__device__ float d_actw[9];

// ---------------- f32x2 packed-FMA helpers ----------------
__device__ __forceinline__ unsigned long long pk2(float lo, float hi) {
    unsigned long long r;
    asm("mov.b64 %0, {%1, %2};" : "=l"(r) : "f"(lo), "f"(hi));
    return r;
}
__device__ __forceinline__ void fma2(unsigned long long& c, unsigned long long a, unsigned long long b) {
    asm("fma.rn.f32x2 %0, %1, %2, %0;" : "+l"(c) : "l"(a), "l"(b));
}
__device__ __forceinline__ float2 upk2(unsigned long long v) {
    float2 r;
    asm("mov.b64 {%0, %1}, %2;" : "=f"(r.x), "=f"(r.y) : "l"(v));
    return r;
}

// ---------------- small helpers ----------------
__device__ __forceinline__ float sigmoidf_(float x) { return 1.0f / (1.0f + expf(-x)); }

__device__ __forceinline__ float qact(float x, const float* w) {
    float sig  = sigmoidf_(x);
    float em1  = expm1f(x);
    float elu  = x > 0.0f ? x : em1;
    float th   = tanhf(x);
    float relu = fmaxf(x, 0.0f);
    float silu = x * sig;
    float gelu = 0.5f * x * (1.0f + erff(x * 0.7071067811865475f));
    const float SELU_L = 1.0507009873554805f, SELU_A = 1.6732632423543772f;
    float selu = SELU_L * (x > 0.0f ? x : SELU_A * em1);
    float sp   = fmaxf(x, 0.0f) + log1pf(expf(-fabsf(x)));   // stable softplus
    float mish = x * tanhf(sp);
    return w[0]*sig + w[1]*elu + w[2]*th + w[3]*relu + w[4]*silu
         + w[5]*gelu + w[6]*selu + w[7]*mish + w[8]*x;
}

// ---------------- prep: softmax(act_w) ----------------
__global__ void prep_actw_kernel(const float* __restrict__ aw) {
    if (threadIdx.x == 0) {
        float m = -1e30f;
        for (int i = 0; i < 9; i++) m = fmaxf(m, aw[i]);
        float e[9], s = 0.0f;
        for (int i = 0; i < 9; i++) { e[i] = expf(aw[i] - m); s += e[i]; }
        float inv = 1.0f / s;
        for (int i = 0; i < 9; i++) d_actw[i] = e[i] * inv;
    }
}

// ---------------- gate = softmax(x @ gate_w + gate_b) ----------------
__global__ void gate_kernel(const float* __restrict__ x,
                            const float* __restrict__ gw,
                            const float* __restrict__ gb) {
    int b = blockIdx.x, t = threadIdx.x;   // 128 threads
    float4 s = make_float4(0.f, 0.f, 0.f, 0.f);
    for (int i = t; i < D_; i += 128) {
        float xv = x[(size_t)b * D_ + i];
        float4 g = *(const float4*)(gw + (size_t)i * 4);
        s.x += xv * g.x; s.y += xv * g.y; s.z += xv * g.z; s.w += xv * g.w;
    }
    __shared__ float4 red[128];
    red[t] = s; __syncthreads();
    for (int off = 64; off > 0; off >>= 1) {
        if (t < off) {
            red[t].x += red[t+off].x; red[t].y += red[t+off].y;
            red[t].z += red[t+off].z; red[t].w += red[t+off].w;
        }
        __syncthreads();
    }
    if (t == 0) {
        float l[4] = { red[0].x + gb[0], red[0].y + gb[1], red[0].z + gb[2], red[0].w + gb[3] };
        float m = fmaxf(fmaxf(l[0], l[1]), fmaxf(l[2], l[3]));
        float e[4], sum = 0.0f;
        for (int n = 0; n < 4; n++) { e[n] = expf(l[n] - m); sum += e[n]; }
        float inv = 1.0f / sum;
        for (int n = 0; n < 4; n++) d_gate[b * 4 + n] = e[n] * inv;
    }
}

// ---------------- xg[b, i*4+n] = x[b,i] * gate[b,n] ----------------
__global__ void xg_kernel(const float* __restrict__ x) {
    int idx = blockIdx.x * blockDim.x + threadIdx.x;   // B_*D_ threads
    if (idx >= B_ * D_) return;
    int b = idx >> 10, i = idx & 1023;
    float xv = x[idx];
    float4 g = *(const float4*)(d_gate + b * 4);
    float4 o = make_float4(xv * g.x, xv * g.y, xv * g.z, xv * g.w);
    *(float4*)(d_xg + (size_t)b * KX + i * 4) = o;
}

// ---------------- w2[(i*4+n), u] = w[i,u,n] ----------------
__global__ void w2t_kernel(const float* __restrict__ w) {
    int idx = blockIdx.x * blockDim.x + threadIdx.x;   // D_*U_ threads
    if (idx >= D_ * U_) return;
    int i = idx >> 11, u = idx & 2047;
    float4 v = *(const float4*)(w + (size_t)idx * 4);  // w[(i*U_+u)*4 + n]
    d_w2[(size_t)(i * 4 + 0) * U_ + u] = v.x;
    d_w2[(size_t)(i * 4 + 1) * U_ + u] = v.y;
    d_w2[(size_t)(i * 4 + 2) * U_ + u] = v.z;
    d_w2[(size_t)(i * 4 + 3) * U_ + u] = v.w;
}

// ---------------- tiled SGEMM with f32x2 FMA ----------------
// C[M,N] = A[M,K] @ B[K,N] (+bias per col)(+act). BM=BN=64, BK=16, 256 thr, 4x4/thread.
// M must be a multiple of 64; K a multiple of 16; N a multiple of 4 (col-guarded).
template<int ACT>   // 0=none, 1=relu, 2=tanh
__global__ void __launch_bounds__(256) sgemm_kernel(
    const float* __restrict__ A, const float* __restrict__ Bm,
    float* __restrict__ C, const float* __restrict__ bias,
    int M, int N, int K, int lda, int ldb, int ldc)
{
    __shared__ float As[16][64];
    __shared__ float Bs[16][64];
    int tid = threadIdx.x;
    int tx = tid & 15, ty = tid >> 4;
    int bm = blockIdx.y * 64, bn = blockIdx.x * 64;

    int am = tid >> 2, ac = (tid & 3) * 4;       // A loader
    int bk = tid >> 4, bnc = (tid & 15) * 4;     // B loader
    bool bok = (bn + bnc) < N;

    unsigned long long acc[4][2];
#pragma unroll
    for (int i = 0; i < 4; i++) { acc[i][0] = 0ull; acc[i][1] = 0ull; }

    const float* Aptr = A + (size_t)(bm + am) * lda + ac;
    const float* Bptr = Bm + (size_t)bk * ldb + bn + bnc;

    for (int k0 = 0; k0 < K; k0 += 16) {
        float4 av = *(const float4*)(Aptr + k0);
        float4 bv = bok ? *(const float4*)(Bptr + (size_t)k0 * ldb)
                        : make_float4(0.f, 0.f, 0.f, 0.f);
        As[ac + 0][am] = av.x; As[ac + 1][am] = av.y;
        As[ac + 2][am] = av.z; As[ac + 3][am] = av.w;
        *(float4*)&Bs[bk][bnc] = bv;
        __syncthreads();
#pragma unroll
        for (int kk = 0; kk < 16; kk++) {
            float4 a = *(const float4*)&As[kk][ty * 4];
            float4 b = *(const float4*)&Bs[kk][tx * 4];
            unsigned long long bp0 = pk2(b.x, b.y), bp1 = pk2(b.z, b.w);
            unsigned long long a0 = pk2(a.x, a.x), a1 = pk2(a.y, a.y);
            unsigned long long a2 = pk2(a.z, a.z), a3 = pk2(a.w, a.w);
            fma2(acc[0][0], a0, bp0); fma2(acc[0][1], a0, bp1);
            fma2(acc[1][0], a1, bp0); fma2(acc[1][1], a1, bp1);
            fma2(acc[2][0], a2, bp0); fma2(acc[2][1], a2, bp1);
            fma2(acc[3][0], a3, bp0); fma2(acc[3][1], a3, bp1);
        }
        __syncthreads();
    }

    int col = bn + tx * 4;
    if (col < N) {
        float4 bb = make_float4(0.f, 0.f, 0.f, 0.f);
        if (bias) bb = *(const float4*)(bias + col);
#pragma unroll
        for (int i = 0; i < 4; i++) {
            int row = bm + ty * 4 + i;
            float2 v0 = upk2(acc[i][0]), v1 = upk2(acc[i][1]);
            float4 v = make_float4(v0.x + bb.x, v0.y + bb.y, v1.x + bb.z, v1.y + bb.w);
            if (ACT == 1) {
                v.x = fmaxf(v.x, 0.f); v.y = fmaxf(v.y, 0.f);
                v.z = fmaxf(v.z, 0.f); v.w = fmaxf(v.w, 0.f);
            } else if (ACT == 2) {
                v.x = tanhf(v.x); v.y = tanhf(v.y); v.z = tanhf(v.z); v.w = tanhf(v.w);
            }
            *(float4*)(C + (size_t)row * ldc + col) = v;
        }
    }
}

// ---------------- hidden = qact(pre + gate·b) * mask ----------------
__global__ void hidden_act_kernel(const float* __restrict__ bvec,
                                  const float* __restrict__ mask) {
    int idx = blockIdx.x * blockDim.x + threadIdx.x;
    if (idx >= B_ * U_) return;
    int b = idx >> 11, u = idx & 2047;
    float4 g  = *(const float4*)(d_gate + b * 4);
    float4 bb = *(const float4*)(bvec + (size_t)u * 4);
    float bias = g.x * bb.x + g.y * bb.y + g.z * bb.z + g.w * bb.w;
    float w[9];
#pragma unroll
    for (int i = 0; i < 9; i++) w[i] = d_actw[i];
    d_hidden[idx] = qact(d_hidden[idx] + bias, w) * mask[u];
}

// ---------------- row softmax (in place) ----------------
__global__ void row_softmax_kernel(float* __restrict__ data, int ncol) {
    float* row = data + (size_t)blockIdx.x * ncol;
    int t = threadIdx.x;   // 256
    __shared__ float red[256];
    float m = -1e30f;
    for (int i = t; i < ncol; i += 256) m = fmaxf(m, row[i]);
    red[t] = m; __syncthreads();
    for (int off = 128; off > 0; off >>= 1) {
        if (t < off) red[t] = fmaxf(red[t], red[t + off]);
        __syncthreads();
    }
    m = red[0]; __syncthreads();
    float s = 0.0f;
    for (int i = t; i < ncol; i += 256) {
        float e = expf(row[i] - m);
        row[i] = e; s += e;
    }
    red[t] = s; __syncthreads();
    for (int off = 128; off > 0; off >>= 1) {
        if (t < off) red[t] += red[t + off];
        __syncthreads();
    }
    float inv = 1.0f / red[0];
    for (int i = t; i < ncol; i += 256) row[i] *= inv;
}

// ---------------- column mean over batch ----------------
__global__ void colmean_kernel(const float* __restrict__ src, float* __restrict__ dst, int ncol) {
    int c = blockIdx.x * blockDim.x + threadIdx.x;
    if (c >= ncol) return;
    float s0 = 0.f, s1 = 0.f, s2 = 0.f, s3 = 0.f;
    for (int b = 0; b < B_; b += 4) {
        s0 += src[(size_t)(b + 0) * ncol + c];
        s1 += src[(size_t)(b + 1) * ncol + c];
        s2 += src[(size_t)(b + 2) * ncol + c];
        s3 += src[(size_t)(b + 3) * ncol + c];
    }
    dst[c] = (s0 + s1 + s2 + s3) * (1.0f / B_);
}

// ---------------- new_mem ----------------
__global__ void newmem_kernel(const float* __restrict__ mem,
                              const float* __restrict__ ug,
                              float* __restrict__ outmem) {
    int idx = blockIdx.x * blockDim.x + threadIdx.x;
    if (idx >= M_ * MD_) return;
    int m = idx >> 10, d = idx & 1023;
    float u = d_cma[m] * ug[m];
    outmem[idx] = mem[idx] * (1.0f - u) + u * d_cmc[d];
}

// ---------------- final: gating + preds scale ----------------
__global__ void final_kernel(const float* __restrict__ cw5,
                             const float* __restrict__ cb5,
                             const float* __restrict__ thr,
                             float* __restrict__ out) {
    int b = blockIdx.x, t = threadIdx.x;   // 128 threads
    __shared__ float red[64];
    __shared__ float gsh;
    if (t < 64) red[t] = d_fused[b * 64 + t] * cw5[t * 2];
    __syncthreads();
    for (int off = 32; off > 0; off >>= 1) {
        if (t < off) red[t] += red[t + off];
        __syncthreads();
    }
    if (t == 0) {
        float o = red[0] + cb5[0];
        gsh = 1.0f / (1.0f + expf(-(o - thr[0])));
    }
    __syncthreads();
    float g = gsh;
    for (int j = t; j < O_; j += 128)
        out[(size_t)b * O_ + j] = d_preds[(size_t)b * O_ + j] * g;
}

// ---------------- launch ----------------
extern "C" void kernel_launch(void* const* d_in, const int* in_sizes, int n_in,
                              void* d_out, int out_size) {
    const float* x      = (const float*)d_in[0];
    const float* w      = (const float*)d_in[1];
    const float* bvec   = (const float*)d_in[2];
    const float* gate_w = (const float*)d_in[3];
    const float* gate_b = (const float*)d_in[4];
    const float* act_w  = (const float*)d_in[5];
    const float* mask   = (const float*)d_in[6];
    const float* mem    = (const float*)d_in[7];
    const float* att_w  = (const float*)d_in[8];
    const float* att_b  = (const float*)d_in[9];
    const float* write_w= (const float*)d_in[10];
    const float* write_b= (const float*)d_in[11];
    const float* upgate = (const float*)d_in[12];
    const float* out_w  = (const float*)d_in[13];
    const float* out_b  = (const float*)d_in[14];
    const float* cw1 = (const float*)d_in[15]; const float* cb1 = (const float*)d_in[16];
    const float* cw2 = (const float*)d_in[17]; const float* cb2 = (const float*)d_in[18];
    const float* cw3 = (const float*)d_in[19]; const float* cb3 = (const float*)d_in[20];
    const float* cw4 = (const float*)d_in[21]; const float* cb4 = (const float*)d_in[22];
    const float* cw5 = (const float*)d_in[23]; const float* cb5 = (const float*)d_in[24];
    const float* thr = (const float*)d_in[25];
    float* out = (float*)d_out;

    float *p_w2, *p_xg, *p_hidden, *p_att, *p_read, *p_cand, *p_preds, *p_feat, *p_fused, *p_cma, *p_cmc;
    cudaGetSymbolAddress((void**)&p_w2, d_w2);
    cudaGetSymbolAddress((void**)&p_xg, d_xg);
    cudaGetSymbolAddress((void**)&p_hidden, d_hidden);
    cudaGetSymbolAddress((void**)&p_att, d_att);
    cudaGetSymbolAddress((void**)&p_read, d_read);
    cudaGetSymbolAddress((void**)&p_cand, d_cand);
    cudaGetSymbolAddress((void**)&p_preds, d_preds);
    cudaGetSymbolAddress((void**)&p_feat, d_feat);
    cudaGetSymbolAddress((void**)&p_fused, d_fused);
    cudaGetSymbolAddress((void**)&p_cma, d_cma);
    cudaGetSymbolAddress((void**)&p_cmc, d_cmc);

    // prep
    prep_actw_kernel<<<1, 32>>>(act_w);
    gate_kernel<<<B_, 128>>>(x, gate_w, gate_b);
    xg_kernel<<<(B_ * D_ + 255) / 256, 256>>>(x);
    w2t_kernel<<<(D_ * U_ + 255) / 256, 256>>>(w);

    // hidden_pre = xg @ w2
    sgemm_kernel<0><<<dim3(U_ / 64, B_ / 64), 256>>>(p_xg, p_w2, p_hidden, nullptr,
                                                     B_, U_, KX, KX, U_, U_);
    hidden_act_kernel<<<(B_ * U_ + 255) / 256, 256>>>(bvec, mask);

    // attention logits -> softmax -> read
    sgemm_kernel<0><<<dim3(M_ / 64, B_ / 64), 256>>>(p_hidden, att_w, p_att, att_b,
                                                     B_, M_, U_, U_, M_, M_);
    row_softmax_kernel<<<B_, 256>>>(p_att, M_);
    sgemm_kernel<0><<<dim3(MD_ / 64, B_ / 64), 256>>>(p_att, mem, p_read, nullptr,
                                                      B_, MD_, M_, M_, MD_, MD_);

    // cand, preds
    sgemm_kernel<2><<<dim3(MD_ / 64, B_ / 64), 256>>>(p_hidden, write_w, p_cand, write_b,
                                                      B_, MD_, U_, U_, MD_, MD_);
    sgemm_kernel<0><<<dim3(O_ / 64, B_ / 64), 256>>>(p_hidden, out_w, p_preds, out_b,
                                                     B_, O_, U_, U_, O_, O_);

    // memory update
    colmean_kernel<<<(M_ + 255) / 256, 256>>>(p_att, p_cma, M_);
    colmean_kernel<<<(MD_ + 255) / 256, 256>>>(p_cand, p_cmc, MD_);
    newmem_kernel<<<(M_ * MD_ + 255) / 256, 256>>>(mem, upgate, out + (size_t)B_ * O_);

    // critic
    sgemm_kernel<1><<<dim3(1, B_ / 64), 256>>>(p_read,  cw1, p_feat + 0,  cb1, B_, 32, MD_, MD_, 32, 96);
    sgemm_kernel<1><<<dim3(1, B_ / 64), 256>>>(p_preds, cw2, p_feat + 32, cb2, B_, 32, O_,  O_,  32, 96);
    sgemm_kernel<1><<<dim3(1, B_ / 64), 256>>>(p_hidden,cw3, p_feat + 64, cb3, B_, 32, U_,  U_,  32, 96);
    sgemm_kernel<1><<<dim3(1, B_ / 64), 256>>>(p_feat,  cw4, p_fused,     cb4, B_, 64, 96,  96,  64, 64);

    final_kernel<<<B_, 128>>>(cw5, cb5, thr, out);
}

// round 2
// speedup vs baseline: 1.0032x; 1.0032x over previous
#include <cuda_runtime.h>
#include <math.h>

// ---------------- problem dims ----------------
#define B_   1024
#define D_   1024
#define U_   2048
#define NB   4
#define M_   2048
#define MD_  1024
#define O_   512
#define KX   (D_*NB)   // 4096

// ---------------- device scratch (allocation-free) ----------------
__device__ float d_w2[KX * U_];        // 32 MB  w transposed to (i*4+n, u)
__device__ float d_xg[B_ * KX];        // 16 MB  x[b,i]*gate[b,n]
__device__ float d_gate[B_ * NB];
__device__ float d_hidden[B_ * U_];    // 8 MB (pre, then activated in place)
__device__ float d_att[B_ * M_];       // 8 MB (logits, then softmax in place)
__device__ float d_read[B_ * MD_];     // 4 MB
__device__ float d_cand[B_ * MD_];     // 4 MB
__device__ float d_preds[B_ * O_];     // 2 MB
__device__ float d_feat[B_ * 96];
__device__ float d_fused[B_ * 64];
__device__ float d_cma[M_];
__device__ float d_cmc[MD_];
__device__ float d_actw[9];

// ---------------- f32x2 packed-FMA helpers ----------------
__device__ __forceinline__ unsigned long long pk2(float lo, float hi) {
    unsigned long long r;
    asm("mov.b64 %0, {%1, %2};" : "=l"(r) : "f"(lo), "f"(hi));
    return r;
}
__device__ __forceinline__ void fma2(unsigned long long& c, unsigned long long a, unsigned long long b) {
    asm("fma.rn.f32x2 %0, %1, %2, %0;" : "+l"(c) : "l"(a), "l"(b));
}
__device__ __forceinline__ float2 upk2(unsigned long long v) {
    float2 r;
    asm("mov.b64 {%0, %1}, %2;" : "=f"(r.x), "=f"(r.y) : "l"(v));
    return r;
}

// ---------------- small helpers ----------------
__device__ __forceinline__ float sigmoidf_(float x) { return 1.0f / (1.0f + expf(-x)); }

__device__ __forceinline__ float qact(float x, const float* w) {
    float sig  = sigmoidf_(x);
    float em1  = expm1f(x);
    float elu  = x > 0.0f ? x : em1;
    float th   = tanhf(x);
    float relu = fmaxf(x, 0.0f);
    float silu = x * sig;
    float gelu = 0.5f * x * (1.0f + erff(x * 0.7071067811865475f));
    const float SELU_L = 1.0507009873554805f, SELU_A = 1.6732632423543772f;
    float selu = SELU_L * (x > 0.0f ? x : SELU_A * em1);
    float sp   = fmaxf(x, 0.0f) + log1pf(expf(-fabsf(x)));   // stable softplus
    float mish = x * tanhf(sp);
    return w[0]*sig + w[1]*elu + w[2]*th + w[3]*relu + w[4]*silu
         + w[5]*gelu + w[6]*selu + w[7]*mish + w[8]*x;
}

// ---------------- prep: softmax(act_w) ----------------
__global__ void prep_actw_kernel(const float* __restrict__ aw) {
    if (threadIdx.x == 0) {
        float m = -1e30f;
        for (int i = 0; i < 9; i++) m = fmaxf(m, aw[i]);
        float e[9], s = 0.0f;
        for (int i = 0; i < 9; i++) { e[i] = expf(aw[i] - m); s += e[i]; }
        float inv = 1.0f / s;
        for (int i = 0; i < 9; i++) d_actw[i] = e[i] * inv;
    }
}

// ---------------- gate = softmax(x @ gate_w + gate_b) ----------------
__global__ void gate_kernel(const float* __restrict__ x,
                            const float* __restrict__ gw,
                            const float* __restrict__ gb) {
    int b = blockIdx.x, t = threadIdx.x;   // 128 threads
    float4 s = make_float4(0.f, 0.f, 0.f, 0.f);
    for (int i = t; i < D_; i += 128) {
        float xv = x[(size_t)b * D_ + i];
        float4 g = *(const float4*)(gw + (size_t)i * 4);
        s.x += xv * g.x; s.y += xv * g.y; s.z += xv * g.z; s.w += xv * g.w;
    }
    __shared__ float4 red[128];
    red[t] = s; __syncthreads();
    for (int off = 64; off > 0; off >>= 1) {
        if (t < off) {
            red[t].x += red[t+off].x; red[t].y += red[t+off].y;
            red[t].z += red[t+off].z; red[t].w += red[t+off].w;
        }
        __syncthreads();
    }
    if (t == 0) {
        float l[4] = { red[0].x + gb[0], red[0].y + gb[1], red[0].z + gb[2], red[0].w + gb[3] };
        float m = fmaxf(fmaxf(l[0], l[1]), fmaxf(l[2], l[3]));
        float e[4], sum = 0.0f;
        for (int n = 0; n < 4; n++) { e[n] = expf(l[n] - m); sum += e[n]; }
        float inv = 1.0f / sum;
        for (int n = 0; n < 4; n++) d_gate[b * 4 + n] = e[n] * inv;
    }
}

// ---------------- xg[b, i*4+n] = x[b,i] * gate[b,n] ----------------
__global__ void xg_kernel(const float* __restrict__ x) {
    int idx = blockIdx.x * blockDim.x + threadIdx.x;   // B_*D_ threads
    if (idx >= B_ * D_) return;
    int b = idx >> 10, i = idx & 1023;
    float xv = x[idx];
    float4 g = *(const float4*)(d_gate + b * 4);
    float4 o = make_float4(xv * g.x, xv * g.y, xv * g.z, xv * g.w);
    *(float4*)(d_xg + (size_t)b * KX + i * 4) = o;
}

// ---------------- w2[(i*4+n), u] = w[i,u,n] ----------------
__global__ void w2t_kernel(const float* __restrict__ w) {
    int idx = blockIdx.x * blockDim.x + threadIdx.x;   // D_*U_ threads
    if (idx >= D_ * U_) return;
    int i = idx >> 11, u = idx & 2047;
    float4 v = *(const float4*)(w + (size_t)idx * 4);  // w[(i*U_+u)*4 + n]
    d_w2[(size_t)(i * 4 + 0) * U_ + u] = v.x;
    d_w2[(size_t)(i * 4 + 1) * U_ + u] = v.y;
    d_w2[(size_t)(i * 4 + 2) * U_ + u] = v.z;
    d_w2[(size_t)(i * 4 + 3) * U_ + u] = v.w;
}

// ---------------- tiled SGEMM with f32x2 FMA ----------------
// C[M,N] = A[M,K] @ B[K,N] (+bias per col)(+act). BM=BN=64, BK=16, 256 thr, 4x4/thread.
// M must be a multiple of 64; K a multiple of 16; N a multiple of 4 (col-guarded).
template<int ACT>   // 0=none, 1=relu, 2=tanh
__global__ void __launch_bounds__(256) sgemm_kernel(
    const float* __restrict__ A, const float* __restrict__ Bm,
    float* __restrict__ C, const float* __restrict__ bias,
    int M, int N, int K, int lda, int ldb, int ldc)
{
    __shared__ float As[16][64];
    __shared__ float Bs[16][64];
    int tid = threadIdx.x;
    int tx = tid & 15, ty = tid >> 4;
    int bm = blockIdx.y * 64, bn = blockIdx.x * 64;

    int am = tid >> 2, ac = (tid & 3) * 4;       // A loader
    int bk = tid >> 4, bnc = (tid & 15) * 4;     // B loader
    bool bok = (bn + bnc) < N;

    unsigned long long acc[4][2];
#pragma unroll
    for (int i = 0; i < 4; i++) { acc[i][0] = 0ull; acc[i][1] = 0ull; }

    const float* Aptr = A + (size_t)(bm + am) * lda + ac;
    const float* Bptr = Bm + (size_t)bk * ldb + bn + bnc;

    for (int k0 = 0; k0 < K; k0 += 16) {
        float4 av = *(const float4*)(Aptr + k0);
        float4 bv = bok ? *(const float4*)(Bptr + (size_t)k0 * ldb)
                        : make_float4(0.f, 0.f, 0.f, 0.f);
        As[ac + 0][am] = av.x; As[ac + 1][am] = av.y;
        As[ac + 2][am] = av.z; As[ac + 3][am] = av.w;
        *(float4*)&Bs[bk][bnc] = bv;
        __syncthreads();
#pragma unroll
        for (int kk = 0; kk < 16; kk++) {
            float4 a = *(const float4*)&As[kk][ty * 4];
            float4 b = *(const float4*)&Bs[kk][tx * 4];
            unsigned long long bp0 = pk2(b.x, b.y), bp1 = pk2(b.z, b.w);
            unsigned long long a0 = pk2(a.x, a.x), a1 = pk2(a.y, a.y);
            unsigned long long a2 = pk2(a.z, a.z), a3 = pk2(a.w, a.w);
            fma2(acc[0][0], a0, bp0); fma2(acc[0][1], a0, bp1);
            fma2(acc[1][0], a1, bp0); fma2(acc[1][1], a1, bp1);
            fma2(acc[2][0], a2, bp0); fma2(acc[2][1], a2, bp1);
            fma2(acc[3][0], a3, bp0); fma2(acc[3][1], a3, bp1);
        }
        __syncthreads();
    }

    int col = bn + tx * 4;
    if (col < N) {
        float4 bb = make_float4(0.f, 0.f, 0.f, 0.f);
        if (bias) bb = *(const float4*)(bias + col);
#pragma unroll
        for (int i = 0; i < 4; i++) {
            int row = bm + ty * 4 + i;
            float2 v0 = upk2(acc[i][0]), v1 = upk2(acc[i][1]);
            float4 v = make_float4(v0.x + bb.x, v0.y + bb.y, v1.x + bb.z, v1.y + bb.w);
            if (ACT == 1) {
                v.x = fmaxf(v.x, 0.f); v.y = fmaxf(v.y, 0.f);
                v.z = fmaxf(v.z, 0.f); v.w = fmaxf(v.w, 0.f);
            } else if (ACT == 2) {
                v.x = tanhf(v.x); v.y = tanhf(v.y); v.z = tanhf(v.z); v.w = tanhf(v.w);
            }
            *(float4*)(C + (size_t)row * ldc + col) = v;
        }
    }
}

// ---------------- hidden = qact(pre + gate·b) * mask ----------------
__global__ void hidden_act_kernel(const float* __restrict__ bvec,
                                  const float* __restrict__ mask) {
    int idx = blockIdx.x * blockDim.x + threadIdx.x;
    if (idx >= B_ * U_) return;
    int b = idx >> 11, u = idx & 2047;
    float4 g  = *(const float4*)(d_gate + b * 4);
    float4 bb = *(const float4*)(bvec + (size_t)u * 4);
    float bias = g.x * bb.x + g.y * bb.y + g.z * bb.z + g.w * bb.w;
    float w[9];
#pragma unroll
    for (int i = 0; i < 9; i++) w[i] = d_actw[i];
    d_hidden[idx] = qact(d_hidden[idx] + bias, w) * mask[u];
}

// ---------------- row softmax (in place) ----------------
__global__ void row_softmax_kernel(float* __restrict__ data, int ncol) {
    float* row = data + (size_t)blockIdx.x * ncol;
    int t = threadIdx.x;   // 256
    __shared__ float red[256];
    float m = -1e30f;
    for (int i = t; i < ncol; i += 256) m = fmaxf(m, row[i]);
    red[t] = m; __syncthreads();
    for (int off = 128; off > 0; off >>= 1) {
        if (t < off) red[t] = fmaxf(red[t], red[t + off]);
        __syncthreads();
    }
    m = red[0]; __syncthreads();
    float s = 0.0f;
    for (int i = t; i < ncol; i += 256) {
        float e = expf(row[i] - m);
        row[i] = e; s += e;
    }
    red[t] = s; __syncthreads();
    for (int off = 128; off > 0; off >>= 1) {
        if (t < off) red[t] += red[t + off];
        __syncthreads();
    }
    float inv = 1.0f / red[0];
    for (int i = t; i < ncol; i += 256) row[i] *= inv;
}

// ---------------- column mean over batch ----------------
__global__ void colmean_kernel(const float* __restrict__ src, float* __restrict__ dst, int ncol) {
    int c = blockIdx.x * blockDim.x + threadIdx.x;
    if (c >= ncol) return;
    float s0 = 0.f, s1 = 0.f, s2 = 0.f, s3 = 0.f;
    for (int b = 0; b < B_; b += 4) {
        s0 += src[(size_t)(b + 0) * ncol + c];
        s1 += src[(size_t)(b + 1) * ncol + c];
        s2 += src[(size_t)(b + 2) * ncol + c];
        s3 += src[(size_t)(b + 3) * ncol + c];
    }
    dst[c] = (s0 + s1 + s2 + s3) * (1.0f / B_);
}

// ---------------- new_mem ----------------
__global__ void newmem_kernel(const float* __restrict__ mem,
                              const float* __restrict__ ug,
                              float* __restrict__ outmem) {
    int idx = blockIdx.x * blockDim.x + threadIdx.x;
    if (idx >= M_ * MD_) return;
    int m = idx >> 10, d = idx & 1023;
    float u = d_cma[m] * ug[m];
    outmem[idx] = mem[idx] * (1.0f - u) + u * d_cmc[d];
}

// ---------------- final: gating + preds scale ----------------
__global__ void final_kernel(const float* __restrict__ cw5,
                             const float* __restrict__ cb5,
                             const float* __restrict__ thr,
                             float* __restrict__ out) {
    int b = blockIdx.x, t = threadIdx.x;   // 128 threads
    __shared__ float red[64];
    __shared__ float gsh;
    if (t < 64) red[t] = d_fused[b * 64 + t] * cw5[t * 2];
    __syncthreads();
    for (int off = 32; off > 0; off >>= 1) {
        if (t < off) red[t] += red[t + off];
        __syncthreads();
    }
    if (t == 0) {
        float o = red[0] + cb5[0];
        gsh = 1.0f / (1.0f + expf(-(o - thr[0])));
    }
    __syncthreads();
    float g = gsh;
    for (int j = t; j < O_; j += 128)
        out[(size_t)b * O_ + j] = d_preds[(size_t)b * O_ + j] * g;
}

// ---------------- launch ----------------
extern "C" void kernel_launch(void* const* d_in, const int* in_sizes, int n_in,
                              void* d_out, int out_size) {
    const float* x      = (const float*)d_in[0];
    const float* w      = (const float*)d_in[1];
    const float* bvec   = (const float*)d_in[2];
    const float* gate_w = (const float*)d_in[3];
    const float* gate_b = (const float*)d_in[4];
    const float* act_w  = (const float*)d_in[5];
    const float* mask   = (const float*)d_in[6];
    const float* mem    = (const float*)d_in[7];
    const float* att_w  = (const float*)d_in[8];
    const float* att_b  = (const float*)d_in[9];
    const float* write_w= (const float*)d_in[10];
    const float* write_b= (const float*)d_in[11];
    const float* upgate = (const float*)d_in[12];
    const float* out_w  = (const float*)d_in[13];
    const float* out_b  = (const float*)d_in[14];
    const float* cw1 = (const float*)d_in[15]; const float* cb1 = (const float*)d_in[16];
    const float* cw2 = (const float*)d_in[17]; const float* cb2 = (const float*)d_in[18];
    const float* cw3 = (const float*)d_in[19]; const float* cb3 = (const float*)d_in[20];
    const float* cw4 = (const float*)d_in[21]; const float* cb4 = (const float*)d_in[22];
    const float* cw5 = (const float*)d_in[23]; const float* cb5 = (const float*)d_in[24];
    const float* thr = (const float*)d_in[25];
    float* out = (float*)d_out;

    float *p_w2, *p_xg, *p_hidden, *p_att, *p_read, *p_cand, *p_preds, *p_feat, *p_fused, *p_cma, *p_cmc;
    cudaGetSymbolAddress((void**)&p_w2, d_w2);
    cudaGetSymbolAddress((void**)&p_xg, d_xg);
    cudaGetSymbolAddress((void**)&p_hidden, d_hidden);
    cudaGetSymbolAddress((void**)&p_att, d_att);
    cudaGetSymbolAddress((void**)&p_read, d_read);
    cudaGetSymbolAddress((void**)&p_cand, d_cand);
    cudaGetSymbolAddress((void**)&p_preds, d_preds);
    cudaGetSymbolAddress((void**)&p_feat, d_feat);
    cudaGetSymbolAddress((void**)&p_fused, d_fused);
    cudaGetSymbolAddress((void**)&p_cma, d_cma);
    cudaGetSymbolAddress((void**)&p_cmc, d_cmc);

    // prep
    prep_actw_kernel<<<1, 32>>>(act_w);
    gate_kernel<<<B_, 128>>>(x, gate_w, gate_b);
    xg_kernel<<<(B_ * D_ + 255) / 256, 256>>>(x);
    w2t_kernel<<<(D_ * U_ + 255) / 256, 256>>>(w);

    // hidden_pre = xg @ w2
    sgemm_kernel<0><<<dim3(U_ / 64, B_ / 64), 256>>>(p_xg, p_w2, p_hidden, nullptr,
                                                     B_, U_, KX, KX, U_, U_);
    hidden_act_kernel<<<(B_ * U_ + 255) / 256, 256>>>(bvec, mask);

    // attention logits -> softmax -> read
    sgemm_kernel<0><<<dim3(M_ / 64, B_ / 64), 256>>>(p_hidden, att_w, p_att, att_b,
                                                     B_, M_, U_, U_, M_, M_);
    row_softmax_kernel<<<B_, 256>>>(p_att, M_);
    sgemm_kernel<0><<<dim3(MD_ / 64, B_ / 64), 256>>>(p_att, mem, p_read, nullptr,
                                                      B_, MD_, M_, M_, MD_, MD_);

    // cand, preds
    sgemm_kernel<2><<<dim3(MD_ / 64, B_ / 64), 256>>>(p_hidden, write_w, p_cand, write_b,
                                                      B_, MD_, U_, U_, MD_, MD_);
    sgemm_kernel<0><<<dim3(O_ / 64, B_ / 64), 256>>>(p_hidden, out_w, p_preds, out_b,
                                                     B_, O_, U_, U_, O_, O_);

    // memory update
    colmean_kernel<<<(M_ + 255) / 256, 256>>>(p_att, p_cma, M_);
    colmean_kernel<<<(MD_ + 255) / 256, 256>>>(p_cand, p_cmc, MD_);
    newmem_kernel<<<(M_ * MD_ + 255) / 256, 256>>>(mem, upgate, out + (size_t)B_ * O_);

    // critic
    sgemm_kernel<1><<<dim3(1, B_ / 64), 256>>>(p_read,  cw1, p_feat + 0,  cb1, B_, 32, MD_, MD_, 32, 96);
    sgemm_kernel<1><<<dim3(1, B_ / 64), 256>>>(p_preds, cw2, p_feat + 32, cb2, B_, 32, O_,  O_,  32, 96);
    sgemm_kernel<1><<<dim3(1, B_ / 64), 256>>>(p_hidden,cw3, p_feat + 64, cb3, B_, 32, U_,  U_,  32, 96);
    sgemm_kernel<1><<<dim3(1, B_ / 64), 256>>>(p_feat,  cw4, p_fused,     cb4, B_, 64, 96,  96,  64, 64);

    final_kernel<<<B_, 128>>>(cw5, cb5, thr, out);
}

// round 4
// speedup vs baseline: 1.6976x; 1.6922x over previous
#include <cuda_runtime.h>
#include <cuda_bf16.h>
#include <cstdint>
#include <math.h>

// ---------------- problem dims ----------------
#define B_   1024
#define D_   1024
#define U_   2048
#define NB   4
#define M_   2048
#define MD_  1024
#define O_   512
#define KX   (D_*NB)   // 4096

// ---------------- device scratch (allocation-free) ----------------
__device__ __nv_bfloat16 d_xgh[B_ * KX],  d_xgl[B_ * KX];     // A of hidden GEMM
__device__ __nv_bfloat16 d_w2h[U_ * KX],  d_w2l[U_ * KX];     // B of hidden GEMM [U][KX]
__device__ __nv_bfloat16 d_awh[M_ * U_],  d_awl[M_ * U_];     // att_w^T [M][U]
__device__ __nv_bfloat16 d_memh[MD_ * M_], d_meml[MD_ * M_];  // mem^T [MD][M]
__device__ __nv_bfloat16 d_wwh[MD_ * U_], d_wwl[MD_ * U_];    // write_w^T [MD][U]
__device__ __nv_bfloat16 d_owh[O_ * U_],  d_owl[O_ * U_];     // out_w^T [O][U]
__device__ float d_gate[B_ * NB];
__device__ float d_hidden[B_ * U_];
__device__ __nv_bfloat16 d_hidh[B_ * U_], d_hidl[B_ * U_];
__device__ float d_att[B_ * M_];
__device__ __nv_bfloat16 d_atth[B_ * M_], d_attl[B_ * M_];
__device__ float d_read[B_ * MD_];
__device__ float d_cand[B_ * MD_];
__device__ float d_preds[B_ * O_];
__device__ float d_feat[B_ * 96];
__device__ float d_fused[B_ * 64];
__device__ float d_cma[M_];
__device__ float d_cmc[MD_];
__device__ float d_actw[9];

// ---------------- bf16 hi/lo split ----------------
__device__ __forceinline__ void split2(float v, __nv_bfloat16& h, __nv_bfloat16& l) {
    h = __float2bfloat16(v);
    l = __float2bfloat16(v - __bfloat162float(h));
}

// ---------------- low-level helpers ----------------
__device__ __forceinline__ uint32_t smem_to_u32(const void* smem_ptr) {
    uint32_t addr;
    asm("{ .reg .u64 tmp; cvta.to.shared.u64 tmp, %1; cvt.u32.u64 %0, tmp; }"
        : "=r"(addr) : "l"(smem_ptr));
    return addr;
}
__device__ __forceinline__ void cp16(uint32_t dst, const void* src) {
    asm volatile("cp.async.cg.shared.global [%0], [%1], 16;" :: "r"(dst), "l"(src));
}
__device__ __forceinline__ uint32_t lds32(uint32_t addr) {
    uint32_t v;
    asm volatile("ld.shared.b32 %0, [%1];" : "=r"(v) : "r"(addr));
    return v;
}
__device__ __forceinline__ void mma16816(float* c, const uint32_t* a, const uint32_t* b) {
    asm volatile(
        "mma.sync.aligned.m16n8k16.row.col.f32.bf16.bf16.f32 "
        "{%0,%1,%2,%3}, {%4,%5,%6,%7}, {%8,%9}, {%0,%1,%2,%3};"
        : "+f"(c[0]), "+f"(c[1]), "+f"(c[2]), "+f"(c[3])
        : "r"(a[0]), "r"(a[1]), "r"(a[2]), "r"(a[3]), "r"(b[0]), "r"(b[1]));
}

// ======================= bf16-split MMA GEMM =======================
// C[M,N] = (Ah+Al)[M,K] @ (Bh+Bl)[N,K]^T  via Ah*Bh + Ah*Bl + Al*Bh, fp32 accum.
// CTA tile 128x128, BK=32, 256 threads (8 warps as 2x4, each warp 64x32).
// SMEM tiles padded to 80B rows => conflict-free LDS.32 fragment loads.
#define MG_STRIDE 80
#define MG_TILE   (128 * MG_STRIDE)          // 10240 B
#define MG_STAGE  (4 * MG_TILE)              // 40960 B (Ah, Al, Bh, Bl)
#define MG_STAGES 3
#define MG_SMEM   (MG_STAGES * MG_STAGE)     // 122880 B

template<int ACT>   // 0=none, 2=tanh
__global__ void __launch_bounds__(256, 1) mgemm_kernel(
    const __nv_bfloat16* __restrict__ Ah, const __nv_bfloat16* __restrict__ Al,
    const __nv_bfloat16* __restrict__ Bh, const __nv_bfloat16* __restrict__ Bl,
    float* __restrict__ C, const float* __restrict__ bias, int K, int N)
{
    extern __shared__ char smem[];
    uint32_t sbase = smem_to_u32(smem);
    int tid = threadIdx.x, wid = tid >> 5, lane = tid & 31;
    int bm = blockIdx.y << 7, bn = blockIdx.x << 7;
    int wm = wid >> 2, wn = wid & 3;             // warp tile (64 x 32)
    int qrow = lane >> 2, qcol = (lane & 3) << 1;

    const __nv_bfloat16* gAh = Ah + (size_t)bm * K;
    const __nv_bfloat16* gAl = Al + (size_t)bm * K;
    const __nv_bfloat16* gBh = Bh + (size_t)bn * K;
    const __nv_bfloat16* gBl = Bl + (size_t)bn * K;

    int row0 = tid >> 2, seg0 = tid & 3;                 // idx = tid
    int row1 = (tid + 256) >> 2, seg1 = tid & 3;         // idx = tid + 256
    uint32_t doff0 = row0 * MG_STRIDE + seg0 * 16;
    uint32_t doff1 = row1 * MG_STRIDE + seg1 * 16;

    int nch = K >> 5;

#define LOAD_CHUNK(c, s) do {                                              \
    uint32_t st_ = sbase + (s) * MG_STAGE;                                 \
    size_t g0_ = (size_t)row0 * K + (c) * 32 + seg0 * 8;                   \
    size_t g1_ = (size_t)row1 * K + (c) * 32 + seg1 * 8;                   \
    cp16(st_ + 0*MG_TILE + doff0, gAh + g0_);                              \
    cp16(st_ + 0*MG_TILE + doff1, gAh + g1_);                              \
    cp16(st_ + 1*MG_TILE + doff0, gAl + g0_);                              \
    cp16(st_ + 1*MG_TILE + doff1, gAl + g1_);                              \
    cp16(st_ + 2*MG_TILE + doff0, gBh + g0_);                              \
    cp16(st_ + 2*MG_TILE + doff1, gBh + g1_);                              \
    cp16(st_ + 3*MG_TILE + doff0, gBl + g0_);                              \
    cp16(st_ + 3*MG_TILE + doff1, gBl + g1_);                              \
    asm volatile("cp.async.commit_group;" ::: "memory");                   \
} while (0)

    int pre = nch < MG_STAGES ? nch : MG_STAGES;
    for (int c = 0; c < pre; c++) LOAD_CHUNK(c, c);

    float acc[4][4][4];
#pragma unroll
    for (int i = 0; i < 4; i++)
#pragma unroll
        for (int j = 0; j < 4; j++)
#pragma unroll
            for (int r = 0; r < 4; r++) acc[i][j][r] = 0.0f;

    for (int c = 0; c < nch; c++) {
        if (c + 3 <= nch)      asm volatile("cp.async.wait_group 2;" ::: "memory");
        else if (c + 2 == nch) asm volatile("cp.async.wait_group 1;" ::: "memory");
        else                   asm volatile("cp.async.wait_group 0;" ::: "memory");
        __syncthreads();

        uint32_t st = sbase + (c % MG_STAGES) * MG_STAGE;
#pragma unroll
        for (int ks = 0; ks < 2; ks++) {
            int k0 = ks << 4;
            uint32_t aH[4][4], aL[4][4], bH[4][2], bL[4][2];
            uint32_t abase = st + (wm * 64 + qrow) * MG_STRIDE + (k0 + qcol) * 2;
#pragma unroll
            for (int mi = 0; mi < 4; mi++) {
                uint32_t p = abase + mi * 16 * MG_STRIDE;
                aH[mi][0] = lds32(p);
                aH[mi][1] = lds32(p + 8 * MG_STRIDE);
                aH[mi][2] = lds32(p + 16);
                aH[mi][3] = lds32(p + 8 * MG_STRIDE + 16);
                aL[mi][0] = lds32(p + MG_TILE);
                aL[mi][1] = lds32(p + MG_TILE + 8 * MG_STRIDE);
                aL[mi][2] = lds32(p + MG_TILE + 16);
                aL[mi][3] = lds32(p + MG_TILE + 8 * MG_STRIDE + 16);
            }
            uint32_t bbase = st + 2 * MG_TILE + (wn * 32 + qrow) * MG_STRIDE + (k0 + qcol) * 2;
#pragma unroll
            for (int nj = 0; nj < 4; nj++) {
                uint32_t p = bbase + nj * 8 * MG_STRIDE;
                bH[nj][0] = lds32(p);
                bH[nj][1] = lds32(p + 16);
                bL[nj][0] = lds32(p + MG_TILE);
                bL[nj][1] = lds32(p + MG_TILE + 16);
            }
#pragma unroll
            for (int mi = 0; mi < 4; mi++)
#pragma unroll
                for (int nj = 0; nj < 4; nj++) {
                    mma16816(acc[mi][nj], aH[mi], bH[nj]);
                    mma16816(acc[mi][nj], aH[mi], bL[nj]);
                    mma16816(acc[mi][nj], aL[mi], bH[nj]);
                }
        }
        __syncthreads();
        if (c + MG_STAGES < nch) LOAD_CHUNK(c + MG_STAGES, (c + MG_STAGES) % MG_STAGES);
    }
#undef LOAD_CHUNK

    // epilogue
#pragma unroll
    for (int mi = 0; mi < 4; mi++) {
        int row = bm + wm * 64 + mi * 16 + qrow;
#pragma unroll
        for (int nj = 0; nj < 4; nj++) {
            int col = bn + wn * 32 + nj * 8 + qcol;
            float b0 = 0.f, b1 = 0.f;
            if (bias) { b0 = bias[col]; b1 = bias[col + 1]; }
            float2 v0 = make_float2(acc[mi][nj][0] + b0, acc[mi][nj][1] + b1);
            float2 v1 = make_float2(acc[mi][nj][2] + b0, acc[mi][nj][3] + b1);
            if (ACT == 2) {
                v0.x = tanhf(v0.x); v0.y = tanhf(v0.y);
                v1.x = tanhf(v1.x); v1.y = tanhf(v1.y);
            }
            *(float2*)(C + (size_t)row * N + col) = v0;
            *(float2*)(C + (size_t)(row + 8) * N + col) = v1;
        }
    }
}

// ======================= FFMA sgemm for tiny critic GEMMs =======================
__device__ __forceinline__ unsigned long long pk2(float lo, float hi) {
    unsigned long long r;
    asm("mov.b64 %0, {%1, %2};" : "=l"(r) : "f"(lo), "f"(hi));
    return r;
}
__device__ __forceinline__ void fma2(unsigned long long& c, unsigned long long a, unsigned long long b) {
    asm("fma.rn.f32x2 %0, %1, %2, %0;" : "+l"(c) : "l"(a), "l"(b));
}
__device__ __forceinline__ float2 upk2(unsigned long long v) {
    float2 r;
    asm("mov.b64 {%0, %1}, %2;" : "=f"(r.x), "=f"(r.y) : "l"(v));
    return r;
}

template<int ACT>   // 0=none, 1=relu
__global__ void __launch_bounds__(256) sgemm_kernel(
    const float* __restrict__ A, const float* __restrict__ Bm,
    float* __restrict__ C, const float* __restrict__ bias,
    int M, int N, int K, int lda, int ldb, int ldc)
{
    __shared__ float As[16][64];
    __shared__ float Bs[16][64];
    int tid = threadIdx.x;
    int tx = tid & 15, ty = tid >> 4;
    int bm = blockIdx.y * 64, bn = blockIdx.x * 64;

    int am = tid >> 2, ac = (tid & 3) * 4;
    int bk = tid >> 4, bnc = (tid & 15) * 4;
    bool bok = (bn + bnc) < N;

    unsigned long long acc[4][2];
#pragma unroll
    for (int i = 0; i < 4; i++) { acc[i][0] = 0ull; acc[i][1] = 0ull; }

    const float* Aptr = A + (size_t)(bm + am) * lda + ac;
    const float* Bptr = Bm + (size_t)bk * ldb + bn + bnc;

    for (int k0 = 0; k0 < K; k0 += 16) {
        float4 av = *(const float4*)(Aptr + k0);
        float4 bv = bok ? *(const float4*)(Bptr + (size_t)k0 * ldb)
                        : make_float4(0.f, 0.f, 0.f, 0.f);
        As[ac + 0][am] = av.x; As[ac + 1][am] = av.y;
        As[ac + 2][am] = av.z; As[ac + 3][am] = av.w;
        *(float4*)&Bs[bk][bnc] = bv;
        __syncthreads();
#pragma unroll
        for (int kk = 0; kk < 16; kk++) {
            float4 a = *(const float4*)&As[kk][ty * 4];
            float4 b = *(const float4*)&Bs[kk][tx * 4];
            unsigned long long bp0 = pk2(b.x, b.y), bp1 = pk2(b.z, b.w);
            unsigned long long a0 = pk2(a.x, a.x), a1 = pk2(a.y, a.y);
            unsigned long long a2 = pk2(a.z, a.z), a3 = pk2(a.w, a.w);
            fma2(acc[0][0], a0, bp0); fma2(acc[0][1], a0, bp1);
            fma2(acc[1][0], a1, bp0); fma2(acc[1][1], a1, bp1);
            fma2(acc[2][0], a2, bp0); fma2(acc[2][1], a2, bp1);
            fma2(acc[3][0], a3, bp0); fma2(acc[3][1], a3, bp1);
        }
        __syncthreads();
    }

    int col = bn + tx * 4;
    if (col < N) {
        float4 bb = make_float4(0.f, 0.f, 0.f, 0.f);
        if (bias) bb = *(const float4*)(bias + col);
#pragma unroll
        for (int i = 0; i < 4; i++) {
            int rrow = bm + ty * 4 + i;
            float2 v0 = upk2(acc[i][0]), v1 = upk2(acc[i][1]);
            float4 v = make_float4(v0.x + bb.x, v0.y + bb.y, v1.x + bb.z, v1.y + bb.w);
            if (ACT == 1) {
                v.x = fmaxf(v.x, 0.f); v.y = fmaxf(v.y, 0.f);
                v.z = fmaxf(v.z, 0.f); v.w = fmaxf(v.w, 0.f);
            }
            *(float4*)(C + (size_t)rrow * ldc + col) = v;
        }
    }
}

// ======================= elementwise / small kernels =======================
__device__ __forceinline__ float sigmoidf_(float x) { return 1.0f / (1.0f + expf(-x)); }

__device__ __forceinline__ float qact(float x, const float* w) {
    float sig  = sigmoidf_(x);
    float em1  = expm1f(x);
    float elu  = x > 0.0f ? x : em1;
    float th   = tanhf(x);
    float relu = fmaxf(x, 0.0f);
    float silu = x * sig;
    float gelu = 0.5f * x * (1.0f + erff(x * 0.7071067811865475f));
    const float SELU_L = 1.0507009873554805f, SELU_A = 1.6732632423543772f;
    float selu = SELU_L * (x > 0.0f ? x : SELU_A * em1);
    float sp   = fmaxf(x, 0.0f) + log1pf(expf(-fabsf(x)));
    float mish = x * tanhf(sp);
    return w[0]*sig + w[1]*elu + w[2]*th + w[3]*relu + w[4]*silu
         + w[5]*gelu + w[6]*selu + w[7]*mish + w[8]*x;
}

__global__ void prep_actw_kernel(const float* __restrict__ aw) {
    if (threadIdx.x == 0) {
        float m = -1e30f;
        for (int i = 0; i < 9; i++) m = fmaxf(m, aw[i]);
        float e[9], s = 0.0f;
        for (int i = 0; i < 9; i++) { e[i] = expf(aw[i] - m); s += e[i]; }
        float inv = 1.0f / s;
        for (int i = 0; i < 9; i++) d_actw[i] = e[i] * inv;
    }
}

__global__ void gate_kernel(const float* __restrict__ x,
                            const float* __restrict__ gw,
                            const float* __restrict__ gb) {
    int b = blockIdx.x, t = threadIdx.x;   // 128 threads
    float4 s = make_float4(0.f, 0.f, 0.f, 0.f);
    for (int i = t; i < D_; i += 128) {
        float xv = x[(size_t)b * D_ + i];
        float4 g = *(const float4*)(gw + (size_t)i * 4);
        s.x += xv * g.x; s.y += xv * g.y; s.z += xv * g.z; s.w += xv * g.w;
    }
    __shared__ float4 red[128];
    red[t] = s; __syncthreads();
    for (int off = 64; off > 0; off >>= 1) {
        if (t < off) {
            red[t].x += red[t+off].x; red[t].y += red[t+off].y;
            red[t].z += red[t+off].z; red[t].w += red[t+off].w;
        }
        __syncthreads();
    }
    if (t == 0) {
        float l[4] = { red[0].x + gb[0], red[0].y + gb[1], red[0].z + gb[2], red[0].w + gb[3] };
        float m = fmaxf(fmaxf(l[0], l[1]), fmaxf(l[2], l[3]));
        float e[4], sum = 0.0f;
        for (int n = 0; n < 4; n++) { e[n] = expf(l[n] - m); sum += e[n]; }
        float inv = 1.0f / sum;
        for (int n = 0; n < 4; n++) d_gate[b * 4 + n] = e[n] * inv;
    }
}

// xg[b, i*4+n] = x[b,i]*gate[b,n]  -> bf16 hi/lo
__global__ void xg_split_kernel(const float* __restrict__ x) {
    int idx = blockIdx.x * blockDim.x + threadIdx.x;
    if (idx >= B_ * D_) return;
    int b = idx >> 10, i = idx & 1023;
    float xv = x[idx];
    float4 g = *(const float4*)(d_gate + b * 4);
    float v[4] = { xv * g.x, xv * g.y, xv * g.z, xv * g.w };
    __nv_bfloat16 h[4], l[4];
#pragma unroll
    for (int n = 0; n < 4; n++) split2(v[n], h[n], l[n]);
    size_t o = (size_t)b * KX + i * 4;
    __nv_bfloat162 t0, t1;
    t0.x = h[0]; t0.y = h[1]; t1.x = h[2]; t1.y = h[3];
    ((__nv_bfloat162*)(d_xgh + o))[0] = t0;
    ((__nv_bfloat162*)(d_xgh + o))[1] = t1;
    t0.x = l[0]; t0.y = l[1]; t1.x = l[2]; t1.y = l[3];
    ((__nv_bfloat162*)(d_xgl + o))[0] = t0;
    ((__nv_bfloat162*)(d_xgl + o))[1] = t1;
}

// w2T[u][i*4+n] = w[i,u,n]  -> bf16 hi/lo, via smem transpose
__global__ void w2t_split_kernel(const float* __restrict__ w) {
    __shared__ float4 s[32][33];
    int u0 = blockIdx.x << 5, i0 = blockIdx.y << 5;
    int tx = threadIdx.x & 31, ty = threadIdx.x >> 5;
    const float4* w4 = (const float4*)w;
    for (int r = ty; r < 32; r += 8)
        s[r][tx] = w4[(size_t)(i0 + r) * U_ + u0 + tx];
    __syncthreads();
    for (int r = ty; r < 32; r += 8) {
        float4 v = s[tx][r];   // i = i0+tx, u = u0+r
        __nv_bfloat16 h[4], l[4];
        split2(v.x, h[0], l[0]); split2(v.y, h[1], l[1]);
        split2(v.z, h[2], l[2]); split2(v.w, h[3], l[3]);
        size_t o = (size_t)(u0 + r) * KX + (i0 + tx) * 4;
        __nv_bfloat162 t0, t1;
        t0.x = h[0]; t0.y = h[1]; t1.x = h[2]; t1.y = h[3];
        ((__nv_bfloat162*)(d_w2h + o))[0] = t0;
        ((__nv_bfloat162*)(d_w2h + o))[1] = t1;
        t0.x = l[0]; t0.y = l[1]; t1.x = l[2]; t1.y = l[3];
        ((__nv_bfloat162*)(d_w2l + o))[0] = t0;
        ((__nv_bfloat162*)(d_w2l + o))[1] = t1;
    }
}

// generic transpose+split: src fp32 [K][N] -> dst bf16 hi/lo [N][K]
__global__ void tsplit_kernel(const float* __restrict__ src,
                              __nv_bfloat16* __restrict__ dh, __nv_bfloat16* __restrict__ dl,
                              int K, int N) {
    __shared__ float s[32][33];
    int n0 = blockIdx.x << 5, k0 = blockIdx.y << 5;
    int tx = threadIdx.x & 31, ty = threadIdx.x >> 5;
    for (int r = ty; r < 32; r += 8)
        s[r][tx] = src[(size_t)(k0 + r) * N + n0 + tx];
    __syncthreads();
    for (int r = ty; r < 32; r += 8) {
        float v = s[tx][r];   // k = k0+tx, n = n0+r
        __nv_bfloat16 h, l;
        split2(v, h, l);
        size_t o = (size_t)(n0 + r) * K + k0 + tx;
        dh[o] = h; dl[o] = l;
    }
}

// hidden = qact(pre + gate·b) * mask ; also bf16 hi/lo
__global__ void hidden_act_split_kernel(const float* __restrict__ bvec,
                                        const float* __restrict__ mask) {
    int idx = blockIdx.x * blockDim.x + threadIdx.x;
    if (idx >= B_ * U_) return;
    int b = idx >> 11, u = idx & 2047;
    float4 g  = *(const float4*)(d_gate + b * 4);
    float4 bb = *(const float4*)(bvec + (size_t)u * 4);
    float bias = g.x * bb.x + g.y * bb.y + g.z * bb.z + g.w * bb.w;
    float w[9];
#pragma unroll
    for (int i = 0; i < 9; i++) w[i] = d_actw[i];
    float hv = qact(d_hidden[idx] + bias, w) * mask[u];
    d_hidden[idx] = hv;
    __nv_bfloat16 h, l;
    split2(hv, h, l);
    d_hidh[idx] = h; d_hidl[idx] = l;
}

// row softmax in place + bf16 hi/lo
__global__ void softmax_split_kernel(float* __restrict__ data,
                                     __nv_bfloat16* __restrict__ oh,
                                     __nv_bfloat16* __restrict__ ol, int ncol) {
    size_t base = (size_t)blockIdx.x * ncol;
    float* row = data + base;
    int t = threadIdx.x;   // 256
    __shared__ float red[256];
    float m = -1e30f;
    for (int i = t; i < ncol; i += 256) m = fmaxf(m, row[i]);
    red[t] = m; __syncthreads();
    for (int off = 128; off > 0; off >>= 1) {
        if (t < off) red[t] = fmaxf(red[t], red[t + off]);
        __syncthreads();
    }
    m = red[0]; __syncthreads();
    float s = 0.0f;
    for (int i = t; i < ncol; i += 256) {
        float e = expf(row[i] - m);
        row[i] = e; s += e;
    }
    red[t] = s; __syncthreads();
    for (int off = 128; off > 0; off >>= 1) {
        if (t < off) red[t] += red[t + off];
        __syncthreads();
    }
    float inv = 1.0f / red[0];
    for (int i = t; i < ncol; i += 256) {
        float v = row[i] * inv;
        row[i] = v;
        __nv_bfloat16 h, l;
        split2(v, h, l);
        oh[base + i] = h; ol[base + i] = l;
    }
}

__global__ void colmean_kernel(const float* __restrict__ src, float* __restrict__ dst, int ncol) {
    int c = blockIdx.x * blockDim.x + threadIdx.x;
    if (c >= ncol) return;
    float s0 = 0.f, s1 = 0.f, s2 = 0.f, s3 = 0.f;
    for (int b = 0; b < B_; b += 4) {
        s0 += src[(size_t)(b + 0) * ncol + c];
        s1 += src[(size_t)(b + 1) * ncol + c];
        s2 += src[(size_t)(b + 2) * ncol + c];
        s3 += src[(size_t)(b + 3) * ncol + c];
    }
    dst[c] = (s0 + s1 + s2 + s3) * (1.0f / B_);
}

__global__ void newmem_kernel(const float* __restrict__ mem,
                              const float* __restrict__ ug,
                              float* __restrict__ outmem) {
    int idx = blockIdx.x * blockDim.x + threadIdx.x;
    if (idx >= M_ * MD_) return;
    int m = idx >> 10, d = idx & 1023;
    float u = d_cma[m] * ug[m];
    outmem[idx] = mem[idx] * (1.0f - u) + u * d_cmc[d];
}

__global__ void final_kernel(const float* __restrict__ cw5,
                             const float* __restrict__ cb5,
                             const float* __restrict__ thr,
                             float* __restrict__ out) {
    int b = blockIdx.x, t = threadIdx.x;   // 128 threads
    __shared__ float red[64];
    __shared__ float gsh;
    if (t < 64) red[t] = d_fused[b * 64 + t] * cw5[t * 2];
    __syncthreads();
    for (int off = 32; off > 0; off >>= 1) {
        if (t < off) red[t] += red[t + off];
        __syncthreads();
    }
    if (t == 0) {
        float o = red[0] + cb5[0];
        gsh = 1.0f / (1.0f + expf(-(o - thr[0])));
    }
    __syncthreads();
    float g = gsh;
    for (int j = t; j < O_; j += 128)
        out[(size_t)b * O_ + j] = d_preds[(size_t)b * O_ + j] * g;
}

// ======================= launch =======================
extern "C" void kernel_launch(void* const* d_in, const int* in_sizes, int n_in,
                              void* d_out, int out_size) {
    const float* x      = (const float*)d_in[0];
    const float* w      = (const float*)d_in[1];
    const float* bvec   = (const float*)d_in[2];
    const float* gate_w = (const float*)d_in[3];
    const float* gate_b = (const float*)d_in[4];
    const float* act_w  = (const float*)d_in[5];
    const float* mask   = (const float*)d_in[6];
    const float* mem    = (const float*)d_in[7];
    const float* att_w  = (const float*)d_in[8];
    const float* att_b  = (const float*)d_in[9];
    const float* write_w= (const float*)d_in[10];
    const float* write_b= (const float*)d_in[11];
    const float* upgate = (const float*)d_in[12];
    const float* out_w  = (const float*)d_in[13];
    const float* out_b  = (const float*)d_in[14];
    const float* cw1 = (const float*)d_in[15]; const float* cb1 = (const float*)d_in[16];
    const float* cw2 = (const float*)d_in[17]; const float* cb2 = (const float*)d_in[18];
    const float* cw3 = (const float*)d_in[19]; const float* cb3 = (const float*)d_in[20];
    const float* cw4 = (const float*)d_in[21]; const float* cb4 = (const float*)d_in[22];
    const float* cw5 = (const float*)d_in[23]; const float* cb5 = (const float*)d_in[24];
    const float* thr = (const float*)d_in[25];
    float* out = (float*)d_out;

    __nv_bfloat16 *p_xgh, *p_xgl, *p_w2h, *p_w2l, *p_awh, *p_awl, *p_memh, *p_meml,
                  *p_wwh, *p_wwl, *p_owh, *p_owl, *p_hidh, *p_hidl, *p_atth, *p_attl;
    float *p_hidden, *p_att, *p_read, *p_cand, *p_preds, *p_feat, *p_fused, *p_cma, *p_cmc;
    cudaGetSymbolAddress((void**)&p_xgh, d_xgh);   cudaGetSymbolAddress((void**)&p_xgl, d_xgl);
    cudaGetSymbolAddress((void**)&p_w2h, d_w2h);   cudaGetSymbolAddress((void**)&p_w2l, d_w2l);
    cudaGetSymbolAddress((void**)&p_awh, d_awh);   cudaGetSymbolAddress((void**)&p_awl, d_awl);
    cudaGetSymbolAddress((void**)&p_memh, d_memh); cudaGetSymbolAddress((void**)&p_meml, d_meml);
    cudaGetSymbolAddress((void**)&p_wwh, d_wwh);   cudaGetSymbolAddress((void**)&p_wwl, d_wwl);
    cudaGetSymbolAddress((void**)&p_owh, d_owh);   cudaGetSymbolAddress((void**)&p_owl, d_owl);
    cudaGetSymbolAddress((void**)&p_hidh, d_hidh); cudaGetSymbolAddress((void**)&p_hidl, d_hidl);
    cudaGetSymbolAddress((void**)&p_atth, d_atth); cudaGetSymbolAddress((void**)&p_attl, d_attl);
    cudaGetSymbolAddress((void**)&p_hidden, d_hidden);
    cudaGetSymbolAddress((void**)&p_att, d_att);
    cudaGetSymbolAddress((void**)&p_read, d_read);
    cudaGetSymbolAddress((void**)&p_cand, d_cand);
    cudaGetSymbolAddress((void**)&p_preds, d_preds);
    cudaGetSymbolAddress((void**)&p_feat, d_feat);
    cudaGetSymbolAddress((void**)&p_fused, d_fused);
    cudaGetSymbolAddress((void**)&p_cma, d_cma);
    cudaGetSymbolAddress((void**)&p_cmc, d_cmc);

    cudaFuncSetAttribute(mgemm_kernel<0>, cudaFuncAttributeMaxDynamicSharedMemorySize, MG_SMEM);
    cudaFuncSetAttribute(mgemm_kernel<2>, cudaFuncAttributeMaxDynamicSharedMemorySize, MG_SMEM);

    // prep + operand conversion
    prep_actw_kernel<<<1, 32>>>(act_w);
    gate_kernel<<<B_, 128>>>(x, gate_w, gate_b);
    xg_split_kernel<<<(B_ * D_ + 255) / 256, 256>>>(x);
    w2t_split_kernel<<<dim3(U_ / 32, D_ / 32), 256>>>(w);
    tsplit_kernel<<<dim3(M_ / 32,  U_ / 32), 256>>>(att_w,   p_awh,  p_awl,  U_, M_);
    tsplit_kernel<<<dim3(MD_ / 32, M_ / 32), 256>>>(mem,     p_memh, p_meml, M_, MD_);
    tsplit_kernel<<<dim3(MD_ / 32, U_ / 32), 256>>>(write_w, p_wwh,  p_wwl,  U_, MD_);
    tsplit_kernel<<<dim3(O_ / 32,  U_ / 32), 256>>>(out_w,   p_owh,  p_owl,  U_, O_);

    // hidden_pre = xg @ w2^T   (1024 x 2048, K=4096)
    mgemm_kernel<0><<<dim3(U_ / 128, B_ / 128), 256, MG_SMEM>>>(
        p_xgh, p_xgl, p_w2h, p_w2l, p_hidden, nullptr, KX, U_);
    hidden_act_split_kernel<<<(B_ * U_ + 255) / 256, 256>>>(bvec, mask);

    // att logits -> softmax -> read
    mgemm_kernel<0><<<dim3(M_ / 128, B_ / 128), 256, MG_SMEM>>>(
        p_hidh, p_hidl, p_awh, p_awl, p_att, att_b, U_, M_);
    softmax_split_kernel<<<B_, 256>>>(p_att, p_atth, p_attl, M_);
    mgemm_kernel<0><<<dim3(MD_ / 128, B_ / 128), 256, MG_SMEM>>>(
        p_atth, p_attl, p_memh, p_meml, p_read, nullptr, M_, MD_);

    // cand (tanh), preds
    mgemm_kernel<2><<<dim3(MD_ / 128, B_ / 128), 256, MG_SMEM>>>(
        p_hidh, p_hidl, p_wwh, p_wwl, p_cand, write_b, U_, MD_);
    mgemm_kernel<0><<<dim3(O_ / 128, B_ / 128), 256, MG_SMEM>>>(
        p_hidh, p_hidl, p_owh, p_owl, p_preds, out_b, U_, O_);

    // memory update
    colmean_kernel<<<(M_ + 255) / 256, 256>>>(p_att, p_cma, M_);
    colmean_kernel<<<(MD_ + 255) / 256, 256>>>(p_cand, p_cmc, MD_);
    newmem_kernel<<<(M_ * MD_ + 255) / 256, 256>>>(mem, upgate, out + (size_t)B_ * O_);

    // critic (tiny, FFMA path)
    sgemm_kernel<1><<<dim3(1, B_ / 64), 256>>>(p_read,  cw1, p_feat + 0,  cb1, B_, 32, MD_, MD_, 32, 96);
    sgemm_kernel<1><<<dim3(1, B_ / 64), 256>>>(p_preds, cw2, p_feat + 32, cb2, B_, 32, O_,  O_,  32, 96);
    sgemm_kernel<1><<<dim3(1, B_ / 64), 256>>>(p_hidden,cw3, p_feat + 64, cb3, B_, 32, U_,  U_,  32, 96);
    sgemm_kernel<1><<<dim3(1, B_ / 64), 256>>>(p_feat,  cw4, p_fused,     cb4, B_, 64, 96,  96,  64, 64);

    final_kernel<<<B_, 128>>>(cw5, cb5, thr, out);
}

// round 5
// speedup vs baseline: 1.7302x; 1.0192x over previous
#include <cuda_runtime.h>
#include <cuda_bf16.h>
#include <cstdint>
#include <math.h>

// ---------------- problem dims ----------------
#define B_   1024
#define D_   1024
#define U_   2048
#define NB   4
#define M_   2048
#define MD_  1024
#define O_   512
#define KX   (D_*NB)   // 4096

// ---------------- device scratch (allocation-free) ----------------
__device__ __nv_bfloat16 d_xgh[B_ * KX],  d_xgl[B_ * KX];     // A of hidden GEMM
__device__ __nv_bfloat16 d_w2h[U_ * KX],  d_w2l[U_ * KX];     // B of hidden GEMM [U][KX]
__device__ __nv_bfloat16 d_awh[M_ * U_],  d_awl[M_ * U_];     // att_w^T [M][U]
__device__ __nv_bfloat16 d_memh[MD_ * M_], d_meml[MD_ * M_];  // mem^T [MD][M]
__device__ __nv_bfloat16 d_wwh[MD_ * U_], d_wwl[MD_ * U_];    // write_w^T [MD][U]
__device__ __nv_bfloat16 d_owh[O_ * U_],  d_owl[O_ * U_];     // out_w^T [O][U]
__device__ float d_gate[B_ * NB];
__device__ float d_hidden[B_ * U_];
__device__ __nv_bfloat16 d_hidh[B_ * U_], d_hidl[B_ * U_];
__device__ float d_att[B_ * M_];
__device__ __nv_bfloat16 d_atth[B_ * M_], d_attl[B_ * M_];
__device__ float d_read[B_ * MD_];
__device__ float d_cand[B_ * MD_];
__device__ float d_preds[B_ * O_];
__device__ float d_feat[B_ * 96];
__device__ float d_fused[B_ * 64];
__device__ float d_cma[M_];
__device__ float d_cmc[MD_];
__device__ float d_actw[9];

// ---------------- bf16 hi/lo split ----------------
__device__ __forceinline__ void split2(float v, __nv_bfloat16& h, __nv_bfloat16& l) {
    h = __float2bfloat16(v);
    l = __float2bfloat16(v - __bfloat162float(h));
}

// ---------------- low-level helpers ----------------
__device__ __forceinline__ uint32_t smem_to_u32(const void* smem_ptr) {
    uint32_t addr;
    asm("{ .reg .u64 tmp; cvta.to.shared.u64 tmp, %1; cvt.u32.u64 %0, tmp; }"
        : "=r"(addr) : "l"(smem_ptr));
    return addr;
}
__device__ __forceinline__ void cp16(uint32_t dst, const void* src) {
    asm volatile("cp.async.cg.shared.global [%0], [%1], 16;" :: "r"(dst), "l"(src));
}
__device__ __forceinline__ void ldsm4(uint32_t* r, uint32_t addr) {
    asm volatile("ldmatrix.sync.aligned.m8n8.x4.shared.b16 {%0,%1,%2,%3}, [%4];"
        : "=r"(r[0]), "=r"(r[1]), "=r"(r[2]), "=r"(r[3]) : "r"(addr));
}
__device__ __forceinline__ void mma16816(float* c, const uint32_t* a, const uint32_t* b) {
    asm volatile(
        "mma.sync.aligned.m16n8k16.row.col.f32.bf16.bf16.f32 "
        "{%0,%1,%2,%3}, {%4,%5,%6,%7}, {%8,%9}, {%0,%1,%2,%3};"
        : "+f"(c[0]), "+f"(c[1]), "+f"(c[2]), "+f"(c[3])
        : "r"(a[0]), "r"(a[1]), "r"(a[2]), "r"(a[3]), "r"(b[0]), "r"(b[1]));
}

// ======================= bf16-split MMA GEMM =======================
// C[M,N] = (Ah+Al)[M,K] @ (Bh+Bl)[N,K]^T  via Ah*Bh + Ah*Bl + Al*Bh, fp32 accum.
// CTA tile 128x128, BK=32, 256 threads (8 warps as 2x4, each warp 64x32).
// SMEM rows padded to 80B => ldmatrix phases provably conflict-free.
#define MG_STRIDE 80
#define MG_TILE   (128 * MG_STRIDE)          // 10240 B
#define MG_STAGE  (4 * MG_TILE)              // 40960 B (Ah, Al, Bh, Bl)
#define MG_STAGES 4
#define MG_SMEM   (MG_STAGES * MG_STAGE)     // 163840 B

template<int ACT>   // 0=none, 2=tanh
__global__ void __launch_bounds__(256, 1) mgemm_kernel(
    const __nv_bfloat16* __restrict__ Ah, const __nv_bfloat16* __restrict__ Al,
    const __nv_bfloat16* __restrict__ Bh, const __nv_bfloat16* __restrict__ Bl,
    float* __restrict__ C, const float* __restrict__ bias, int K, int N)
{
    extern __shared__ char smem[];
    uint32_t sbase = smem_to_u32(smem);
    int tid = threadIdx.x, wid = tid >> 5, lane = tid & 31;
    int bm = blockIdx.y << 7, bn = blockIdx.x << 7;
    int wm = wid >> 2, wn = wid & 3;             // warp tile (64 x 32)
    int qrow = lane >> 2, qcol = (lane & 3) << 1;

    const __nv_bfloat16* gAh = Ah + (size_t)bm * K;
    const __nv_bfloat16* gAl = Al + (size_t)bm * K;
    const __nv_bfloat16* gBh = Bh + (size_t)bn * K;
    const __nv_bfloat16* gBl = Bl + (size_t)bn * K;

    int row0 = tid >> 2, seg0 = tid & 3;                 // idx = tid
    int row1 = (tid + 256) >> 2, seg1 = tid & 3;         // idx = tid + 256
    uint32_t doff0 = row0 * MG_STRIDE + seg0 * 16;
    uint32_t doff1 = row1 * MG_STRIDE + seg1 * 16;

    // ldmatrix per-thread fragment base offsets (bytes within one tile)
    //  A (x4): lanes 0-7 rows m0-7@k0 | 8-15 m8-15@k0 | 16-23 m0-7@k8 | 24-31 m8-15@k8
    uint32_t a_off = (wm * 64 + (lane & 15)) * MG_STRIDE + (lane >> 4) * 16;
    //  B (x4, two n-blocks): 0-7 n0-7@k0 | 8-15 n0-7@k8 | 16-23 n8-15@k0 | 24-31 n8-15@k8
    uint32_t b_off = (wn * 32 + (lane & 7) + ((lane >> 4) & 1) * 8) * MG_STRIDE
                   + ((lane >> 3) & 1) * 16;

    int nch = K >> 5;

#define LOAD_CHUNK(c, s) do {                                              \
    uint32_t st_ = sbase + (s) * MG_STAGE;                                 \
    size_t g0_ = (size_t)row0 * K + (c) * 32 + seg0 * 8;                   \
    size_t g1_ = (size_t)row1 * K + (c) * 32 + seg1 * 8;                   \
    cp16(st_ + 0*MG_TILE + doff0, gAh + g0_);                              \
    cp16(st_ + 0*MG_TILE + doff1, gAh + g1_);                              \
    cp16(st_ + 1*MG_TILE + doff0, gAl + g0_);                              \
    cp16(st_ + 1*MG_TILE + doff1, gAl + g1_);                              \
    cp16(st_ + 2*MG_TILE + doff0, gBh + g0_);                              \
    cp16(st_ + 2*MG_TILE + doff1, gBh + g1_);                              \
    cp16(st_ + 3*MG_TILE + doff0, gBl + g0_);                              \
    cp16(st_ + 3*MG_TILE + doff1, gBl + g1_);                              \
    asm volatile("cp.async.commit_group;" ::: "memory");                   \
} while (0)

    int pre = nch < MG_STAGES ? nch : MG_STAGES;
    for (int c = 0; c < pre; c++) LOAD_CHUNK(c, c);

    float acc[4][4][4];
#pragma unroll
    for (int i = 0; i < 4; i++)
#pragma unroll
        for (int j = 0; j < 4; j++)
#pragma unroll
            for (int r = 0; r < 4; r++) acc[i][j][r] = 0.0f;

    for (int c = 0; c < nch; c++) {
        {   // wait until chunk c resident: allowed pending = min(S-1, nch-c-1)
            int kw = nch - c - 1; if (kw > MG_STAGES - 1) kw = MG_STAGES - 1;
            if (kw >= 3)      asm volatile("cp.async.wait_group 3;" ::: "memory");
            else if (kw == 2) asm volatile("cp.async.wait_group 2;" ::: "memory");
            else if (kw == 1) asm volatile("cp.async.wait_group 1;" ::: "memory");
            else              asm volatile("cp.async.wait_group 0;" ::: "memory");
        }
        __syncthreads();

        uint32_t st = sbase + (c % MG_STAGES) * MG_STAGE;
#pragma unroll
        for (int ks = 0; ks < 2; ks++) {
            uint32_t kb = ks * 32;   // k16-step byte offset
            uint32_t aH[4][4], aL[4][4], bH[2][4], bL[2][4];
#pragma unroll
            for (int mi = 0; mi < 4; mi++) {
                uint32_t p = st + a_off + mi * 16 * MG_STRIDE + kb;
                ldsm4(aH[mi], p);
                ldsm4(aL[mi], p + MG_TILE);
            }
#pragma unroll
            for (int njp = 0; njp < 2; njp++) {
                uint32_t p = st + 2 * MG_TILE + b_off + njp * 16 * MG_STRIDE + kb;
                ldsm4(bH[njp], p);
                ldsm4(bL[njp], p + MG_TILE);
            }
#pragma unroll
            for (int mi = 0; mi < 4; mi++)
#pragma unroll
                for (int njp = 0; njp < 2; njp++)
#pragma unroll
                    for (int sub = 0; sub < 2; sub++) {
                        float* a_ = acc[mi][njp * 2 + sub];
                        mma16816(a_, aH[mi], &bH[njp][sub * 2]);
                        mma16816(a_, aH[mi], &bL[njp][sub * 2]);
                        mma16816(a_, aL[mi], &bH[njp][sub * 2]);
                    }
        }
        __syncthreads();
        if (c + MG_STAGES < nch) LOAD_CHUNK(c + MG_STAGES, (c + MG_STAGES) % MG_STAGES);
    }
#undef LOAD_CHUNK

    // epilogue
#pragma unroll
    for (int mi = 0; mi < 4; mi++) {
        int row = bm + wm * 64 + mi * 16 + qrow;
#pragma unroll
        for (int nj = 0; nj < 4; nj++) {
            int col = bn + wn * 32 + nj * 8 + qcol;
            float b0 = 0.f, b1 = 0.f;
            if (bias) { b0 = bias[col]; b1 = bias[col + 1]; }
            float2 v0 = make_float2(acc[mi][nj][0] + b0, acc[mi][nj][1] + b1);
            float2 v1 = make_float2(acc[mi][nj][2] + b0, acc[mi][nj][3] + b1);
            if (ACT == 2) {
                v0.x = tanhf(v0.x); v0.y = tanhf(v0.y);
                v1.x = tanhf(v1.x); v1.y = tanhf(v1.y);
            }
            *(float2*)(C + (size_t)row * N + col) = v0;
            *(float2*)(C + (size_t)(row + 8) * N + col) = v1;
        }
    }
}

// ======================= FFMA sgemm for tiny critic GEMMs =======================
__device__ __forceinline__ unsigned long long pk2(float lo, float hi) {
    unsigned long long r;
    asm("mov.b64 %0, {%1, %2};" : "=l"(r) : "f"(lo), "f"(hi));
    return r;
}
__device__ __forceinline__ void fma2(unsigned long long& c, unsigned long long a, unsigned long long b) {
    asm("fma.rn.f32x2 %0, %1, %2, %0;" : "+l"(c) : "l"(a), "l"(b));
}
__device__ __forceinline__ float2 upk2(unsigned long long v) {
    float2 r;
    asm("mov.b64 {%0, %1}, %2;" : "=f"(r.x), "=f"(r.y) : "l"(v));
    return r;
}

template<int ACT>   // 0=none, 1=relu
__global__ void __launch_bounds__(256) sgemm_kernel(
    const float* __restrict__ A, const float* __restrict__ Bm,
    float* __restrict__ C, const float* __restrict__ bias,
    int M, int N, int K, int lda, int ldb, int ldc)
{
    __shared__ float As[16][64];
    __shared__ float Bs[16][64];
    int tid = threadIdx.x;
    int tx = tid & 15, ty = tid >> 4;
    int bm = blockIdx.y * 64, bn = blockIdx.x * 64;

    int am = tid >> 2, ac = (tid & 3) * 4;
    int bk = tid >> 4, bnc = (tid & 15) * 4;
    bool bok = (bn + bnc) < N;

    unsigned long long acc[4][2];
#pragma unroll
    for (int i = 0; i < 4; i++) { acc[i][0] = 0ull; acc[i][1] = 0ull; }

    const float* Aptr = A + (size_t)(bm + am) * lda + ac;
    const float* Bptr = Bm + (size_t)bk * ldb + bn + bnc;

    for (int k0 = 0; k0 < K; k0 += 16) {
        float4 av = *(const float4*)(Aptr + k0);
        float4 bv = bok ? *(const float4*)(Bptr + (size_t)k0 * ldb)
                        : make_float4(0.f, 0.f, 0.f, 0.f);
        As[ac + 0][am] = av.x; As[ac + 1][am] = av.y;
        As[ac + 2][am] = av.z; As[ac + 3][am] = av.w;
        *(float4*)&Bs[bk][bnc] = bv;
        __syncthreads();
#pragma unroll
        for (int kk = 0; kk < 16; kk++) {
            float4 a = *(const float4*)&As[kk][ty * 4];
            float4 b = *(const float4*)&Bs[kk][tx * 4];
            unsigned long long bp0 = pk2(b.x, b.y), bp1 = pk2(b.z, b.w);
            unsigned long long a0 = pk2(a.x, a.x), a1 = pk2(a.y, a.y);
            unsigned long long a2 = pk2(a.z, a.z), a3 = pk2(a.w, a.w);
            fma2(acc[0][0], a0, bp0); fma2(acc[0][1], a0, bp1);
            fma2(acc[1][0], a1, bp0); fma2(acc[1][1], a1, bp1);
            fma2(acc[2][0], a2, bp0); fma2(acc[2][1], a2, bp1);
            fma2(acc[3][0], a3, bp0); fma2(acc[3][1], a3, bp1);
        }
        __syncthreads();
    }

    int col = bn + tx * 4;
    if (col < N) {
        float4 bb = make_float4(0.f, 0.f, 0.f, 0.f);
        if (bias) bb = *(const float4*)(bias + col);
#pragma unroll
        for (int i = 0; i < 4; i++) {
            int rrow = bm + ty * 4 + i;
            float2 v0 = upk2(acc[i][0]), v1 = upk2(acc[i][1]);
            float4 v = make_float4(v0.x + bb.x, v0.y + bb.y, v1.x + bb.z, v1.y + bb.w);
            if (ACT == 1) {
                v.x = fmaxf(v.x, 0.f); v.y = fmaxf(v.y, 0.f);
                v.z = fmaxf(v.z, 0.f); v.w = fmaxf(v.w, 0.f);
            }
            *(float4*)(C + (size_t)rrow * ldc + col) = v;
        }
    }
}

// ======================= elementwise / small kernels =======================
__device__ __forceinline__ float sigmoidf_(float x) { return 1.0f / (1.0f + expf(-x)); }

__device__ __forceinline__ float qact(float x, const float* w) {
    float sig  = sigmoidf_(x);
    float em1  = expm1f(x);
    float elu  = x > 0.0f ? x : em1;
    float th   = tanhf(x);
    float relu = fmaxf(x, 0.0f);
    float silu = x * sig;
    float gelu = 0.5f * x * (1.0f + erff(x * 0.7071067811865475f));
    const float SELU_L = 1.0507009873554805f, SELU_A = 1.6732632423543772f;
    float selu = SELU_L * (x > 0.0f ? x : SELU_A * em1);
    float sp   = fmaxf(x, 0.0f) + log1pf(expf(-fabsf(x)));
    float mish = x * tanhf(sp);
    return w[0]*sig + w[1]*elu + w[2]*th + w[3]*relu + w[4]*silu
         + w[5]*gelu + w[6]*selu + w[7]*mish + w[8]*x;
}

__global__ void prep_actw_kernel(const float* __restrict__ aw) {
    if (threadIdx.x == 0) {
        float m = -1e30f;
        for (int i = 0; i < 9; i++) m = fmaxf(m, aw[i]);
        float e[9], s = 0.0f;
        for (int i = 0; i < 9; i++) { e[i] = expf(aw[i] - m); s += e[i]; }
        float inv = 1.0f / s;
        for (int i = 0; i < 9; i++) d_actw[i] = e[i] * inv;
    }
}

__global__ void gate_kernel(const float* __restrict__ x,
                            const float* __restrict__ gw,
                            const float* __restrict__ gb) {
    int b = blockIdx.x, t = threadIdx.x;   // 128 threads
    float4 s = make_float4(0.f, 0.f, 0.f, 0.f);
    for (int i = t; i < D_; i += 128) {
        float xv = x[(size_t)b * D_ + i];
        float4 g = *(const float4*)(gw + (size_t)i * 4);
        s.x += xv * g.x; s.y += xv * g.y; s.z += xv * g.z; s.w += xv * g.w;
    }
    __shared__ float4 red[128];
    red[t] = s; __syncthreads();
    for (int off = 64; off > 0; off >>= 1) {
        if (t < off) {
            red[t].x += red[t+off].x; red[t].y += red[t+off].y;
            red[t].z += red[t+off].z; red[t].w += red[t+off].w;
        }
        __syncthreads();
    }
    if (t == 0) {
        float l[4] = { red[0].x + gb[0], red[0].y + gb[1], red[0].z + gb[2], red[0].w + gb[3] };
        float m = fmaxf(fmaxf(l[0], l[1]), fmaxf(l[2], l[3]));
        float e[4], sum = 0.0f;
        for (int n = 0; n < 4; n++) { e[n] = expf(l[n] - m); sum += e[n]; }
        float inv = 1.0f / sum;
        for (int n = 0; n < 4; n++) d_gate[b * 4 + n] = e[n] * inv;
    }
}

// xg[b, i*4+n] = x[b,i]*gate[b,n]  -> bf16 hi/lo
__global__ void xg_split_kernel(const float* __restrict__ x) {
    int idx = blockIdx.x * blockDim.x + threadIdx.x;
    if (idx >= B_ * D_) return;
    int b = idx >> 10, i = idx & 1023;
    float xv = x[idx];
    float4 g = *(const float4*)(d_gate + b * 4);
    float v[4] = { xv * g.x, xv * g.y, xv * g.z, xv * g.w };
    __nv_bfloat16 h[4], l[4];
#pragma unroll
    for (int n = 0; n < 4; n++) split2(v[n], h[n], l[n]);
    size_t o = (size_t)b * KX + i * 4;
    __nv_bfloat162 t0, t1;
    t0.x = h[0]; t0.y = h[1]; t1.x = h[2]; t1.y = h[3];
    ((__nv_bfloat162*)(d_xgh + o))[0] = t0;
    ((__nv_bfloat162*)(d_xgh + o))[1] = t1;
    t0.x = l[0]; t0.y = l[1]; t1.x = l[2]; t1.y = l[3];
    ((__nv_bfloat162*)(d_xgl + o))[0] = t0;
    ((__nv_bfloat162*)(d_xgl + o))[1] = t1;
}

// w2T[u][i*4+n] = w[i,u,n]  -> bf16 hi/lo, via smem transpose
__global__ void w2t_split_kernel(const float* __restrict__ w) {
    __shared__ float4 s[32][33];
    int u0 = blockIdx.x << 5, i0 = blockIdx.y << 5;
    int tx = threadIdx.x & 31, ty = threadIdx.x >> 5;
    const float4* w4 = (const float4*)w;
    for (int r = ty; r < 32; r += 8)
        s[r][tx] = w4[(size_t)(i0 + r) * U_ + u0 + tx];
    __syncthreads();
    for (int r = ty; r < 32; r += 8) {
        float4 v = s[tx][r];   // i = i0+tx, u = u0+r
        __nv_bfloat16 h[4], l[4];
        split2(v.x, h[0], l[0]); split2(v.y, h[1], l[1]);
        split2(v.z, h[2], l[2]); split2(v.w, h[3], l[3]);
        size_t o = (size_t)(u0 + r) * KX + (i0 + tx) * 4;
        __nv_bfloat162 t0, t1;
        t0.x = h[0]; t0.y = h[1]; t1.x = h[2]; t1.y = h[3];
        ((__nv_bfloat162*)(d_w2h + o))[0] = t0;
        ((__nv_bfloat162*)(d_w2h + o))[1] = t1;
        t0.x = l[0]; t0.y = l[1]; t1.x = l[2]; t1.y = l[3];
        ((__nv_bfloat162*)(d_w2l + o))[0] = t0;
        ((__nv_bfloat162*)(d_w2l + o))[1] = t1;
    }
}

// generic transpose+split: src fp32 [K][N] -> dst bf16 hi/lo [N][K]
__global__ void tsplit_kernel(const float* __restrict__ src,
                              __nv_bfloat16* __restrict__ dh, __nv_bfloat16* __restrict__ dl,
                              int K, int N) {
    __shared__ float s[32][33];
    int n0 = blockIdx.x << 5, k0 = blockIdx.y << 5;
    int tx = threadIdx.x & 31, ty = threadIdx.x >> 5;
    for (int r = ty; r < 32; r += 8)
        s[r][tx] = src[(size_t)(k0 + r) * N + n0 + tx];
    __syncthreads();
    for (int r = ty; r < 32; r += 8) {
        float v = s[tx][r];   // k = k0+tx, n = n0+r
        __nv_bfloat16 h, l;
        split2(v, h, l);
        size_t o = (size_t)(n0 + r) * K + k0 + tx;
        dh[o] = h; dl[o] = l;
    }
}

// hidden = qact(pre + gate·b) * mask ; also bf16 hi/lo
__global__ void hidden_act_split_kernel(const float* __restrict__ bvec,
                                        const float* __restrict__ mask) {
    int idx = blockIdx.x * blockDim.x + threadIdx.x;
    if (idx >= B_ * U_) return;
    int b = idx >> 11, u = idx & 2047;
    float4 g  = *(const float4*)(d_gate + b * 4);
    float4 bb = *(const float4*)(bvec + (size_t)u * 4);
    float bias = g.x * bb.x + g.y * bb.y + g.z * bb.z + g.w * bb.w;
    float w[9];
#pragma unroll
    for (int i = 0; i < 9; i++) w[i] = d_actw[i];
    float hv = qact(d_hidden[idx] + bias, w) * mask[u];
    d_hidden[idx] = hv;
    __nv_bfloat16 h, l;
    split2(hv, h, l);
    d_hidh[idx] = h; d_hidl[idx] = l;
}

// row softmax in place + bf16 hi/lo
__global__ void softmax_split_kernel(float* __restrict__ data,
                                     __nv_bfloat16* __restrict__ oh,
                                     __nv_bfloat16* __restrict__ ol, int ncol) {
    size_t base = (size_t)blockIdx.x * ncol;
    float* row = data + base;
    int t = threadIdx.x;   // 256
    __shared__ float red[256];
    float m = -1e30f;
    for (int i = t; i < ncol; i += 256) m = fmaxf(m, row[i]);
    red[t] = m; __syncthreads();
    for (int off = 128; off > 0; off >>= 1) {
        if (t < off) red[t] = fmaxf(red[t], red[t + off]);
        __syncthreads();
    }
    m = red[0]; __syncthreads();
    float s = 0.0f;
    for (int i = t; i < ncol; i += 256) {
        float e = expf(row[i] - m);
        row[i] = e; s += e;
    }
    red[t] = s; __syncthreads();
    for (int off = 128; off > 0; off >>= 1) {
        if (t < off) red[t] += red[t + off];
        __syncthreads();
    }
    float inv = 1.0f / red[0];
    for (int i = t; i < ncol; i += 256) {
        float v = row[i] * inv;
        row[i] = v;
        __nv_bfloat16 h, l;
        split2(v, h, l);
        oh[base + i] = h; ol[base + i] = l;
    }
}

__global__ void colmean_kernel(const float* __restrict__ src, float* __restrict__ dst, int ncol) {
    int c = blockIdx.x * blockDim.x + threadIdx.x;
    if (c >= ncol) return;
    float s0 = 0.f, s1 = 0.f, s2 = 0.f, s3 = 0.f;
    for (int b = 0; b < B_; b += 4) {
        s0 += src[(size_t)(b + 0) * ncol + c];
        s1 += src[(size_t)(b + 1) * ncol + c];
        s2 += src[(size_t)(b + 2) * ncol + c];
        s3 += src[(size_t)(b + 3) * ncol + c];
    }
    dst[c] = (s0 + s1 + s2 + s3) * (1.0f / B_);
}

__global__ void newmem_kernel(const float* __restrict__ mem,
                              const float* __restrict__ ug,
                              float* __restrict__ outmem) {
    int idx = blockIdx.x * blockDim.x + threadIdx.x;
    if (idx >= M_ * MD_) return;
    int m = idx >> 10, d = idx & 1023;
    float u = d_cma[m] * ug[m];
    outmem[idx] = mem[idx] * (1.0f - u) + u * d_cmc[d];
}

__global__ void final_kernel(const float* __restrict__ cw5,
                             const float* __restrict__ cb5,
                             const float* __restrict__ thr,
                             float* __restrict__ out) {
    int b = blockIdx.x, t = threadIdx.x;   // 128 threads
    __shared__ float red[64];
    __shared__ float gsh;
    if (t < 64) red[t] = d_fused[b * 64 + t] * cw5[t * 2];
    __syncthreads();
    for (int off = 32; off > 0; off >>= 1) {
        if (t < off) red[t] += red[t + off];
        __syncthreads();
    }
    if (t == 0) {
        float o = red[0] + cb5[0];
        gsh = 1.0f / (1.0f + expf(-(o - thr[0])));
    }
    __syncthreads();
    float g = gsh;
    for (int j = t; j < O_; j += 128)
        out[(size_t)b * O_ + j] = d_preds[(size_t)b * O_ + j] * g;
}

// ======================= launch =======================
extern "C" void kernel_launch(void* const* d_in, const int* in_sizes, int n_in,
                              void* d_out, int out_size) {
    const float* x      = (const float*)d_in[0];
    const float* w      = (const float*)d_in[1];
    const float* bvec   = (const float*)d_in[2];
    const float* gate_w = (const float*)d_in[3];
    const float* gate_b = (const float*)d_in[4];
    const float* act_w  = (const float*)d_in[5];
    const float* mask   = (const float*)d_in[6];
    const float* mem    = (const float*)d_in[7];
    const float* att_w  = (const float*)d_in[8];
    const float* att_b  = (const float*)d_in[9];
    const float* write_w= (const float*)d_in[10];
    const float* write_b= (const float*)d_in[11];
    const float* upgate = (const float*)d_in[12];
    const float* out_w  = (const float*)d_in[13];
    const float* out_b  = (const float*)d_in[14];
    const float* cw1 = (const float*)d_in[15]; const float* cb1 = (const float*)d_in[16];
    const float* cw2 = (const float*)d_in[17]; const float* cb2 = (const float*)d_in[18];
    const float* cw3 = (const float*)d_in[19]; const float* cb3 = (const float*)d_in[20];
    const float* cw4 = (const float*)d_in[21]; const float* cb4 = (const float*)d_in[22];
    const float* cw5 = (const float*)d_in[23]; const float* cb5 = (const float*)d_in[24];
    const float* thr = (const float*)d_in[25];
    float* out = (float*)d_out;

    __nv_bfloat16 *p_xgh, *p_xgl, *p_w2h, *p_w2l, *p_awh, *p_awl, *p_memh, *p_meml,
                  *p_wwh, *p_wwl, *p_owh, *p_owl, *p_hidh, *p_hidl, *p_atth, *p_attl;
    float *p_hidden, *p_att, *p_read, *p_cand, *p_preds, *p_feat, *p_fused, *p_cma, *p_cmc;
    cudaGetSymbolAddress((void**)&p_xgh, d_xgh);   cudaGetSymbolAddress((void**)&p_xgl, d_xgl);
    cudaGetSymbolAddress((void**)&p_w2h, d_w2h);   cudaGetSymbolAddress((void**)&p_w2l, d_w2l);
    cudaGetSymbolAddress((void**)&p_awh, d_awh);   cudaGetSymbolAddress((void**)&p_awl, d_awl);
    cudaGetSymbolAddress((void**)&p_memh, d_memh); cudaGetSymbolAddress((void**)&p_meml, d_meml);
    cudaGetSymbolAddress((void**)&p_wwh, d_wwh);   cudaGetSymbolAddress((void**)&p_wwl, d_wwl);
    cudaGetSymbolAddress((void**)&p_owh, d_owh);   cudaGetSymbolAddress((void**)&p_owl, d_owl);
    cudaGetSymbolAddress((void**)&p_hidh, d_hidh); cudaGetSymbolAddress((void**)&p_hidl, d_hidl);
    cudaGetSymbolAddress((void**)&p_atth, d_atth); cudaGetSymbolAddress((void**)&p_attl, d_attl);
    cudaGetSymbolAddress((void**)&p_hidden, d_hidden);
    cudaGetSymbolAddress((void**)&p_att, d_att);
    cudaGetSymbolAddress((void**)&p_read, d_read);
    cudaGetSymbolAddress((void**)&p_cand, d_cand);
    cudaGetSymbolAddress((void**)&p_preds, d_preds);
    cudaGetSymbolAddress((void**)&p_feat, d_feat);
    cudaGetSymbolAddress((void**)&p_fused, d_fused);
    cudaGetSymbolAddress((void**)&p_cma, d_cma);
    cudaGetSymbolAddress((void**)&p_cmc, d_cmc);

    cudaFuncSetAttribute(mgemm_kernel<0>, cudaFuncAttributeMaxDynamicSharedMemorySize, MG_SMEM);
    cudaFuncSetAttribute(mgemm_kernel<2>, cudaFuncAttributeMaxDynamicSharedMemorySize, MG_SMEM);

    // prep + operand conversion
    prep_actw_kernel<<<1, 32>>>(act_w);
    gate_kernel<<<B_, 128>>>(x, gate_w, gate_b);
    xg_split_kernel<<<(B_ * D_ + 255) / 256, 256>>>(x);
    w2t_split_kernel<<<dim3(U_ / 32, D_ / 32), 256>>>(w);
    tsplit_kernel<<<dim3(M_ / 32,  U_ / 32), 256>>>(att_w,   p_awh,  p_awl,  U_, M_);
    tsplit_kernel<<<dim3(MD_ / 32, M_ / 32), 256>>>(mem,     p_memh, p_meml, M_, MD_);
    tsplit_kernel<<<dim3(MD_ / 32, U_ / 32), 256>>>(write_w, p_wwh,  p_wwl,  U_, MD_);
    tsplit_kernel<<<dim3(O_ / 32,  U_ / 32), 256>>>(out_w,   p_owh,  p_owl,  U_, O_);

    // hidden_pre = xg @ w2^T   (1024 x 2048, K=4096)
    mgemm_kernel<0><<<dim3(U_ / 128, B_ / 128), 256, MG_SMEM>>>(
        p_xgh, p_xgl, p_w2h, p_w2l, p_hidden, nullptr, KX, U_);
    hidden_act_split_kernel<<<(B_ * U_ + 255) / 256, 256>>>(bvec, mask);

    // att logits -> softmax -> read
    mgemm_kernel<0><<<dim3(M_ / 128, B_ / 128), 256, MG_SMEM>>>(
        p_hidh, p_hidl, p_awh, p_awl, p_att, att_b, U_, M_);
    softmax_split_kernel<<<B_, 256>>>(p_att, p_atth, p_attl, M_);
    mgemm_kernel<0><<<dim3(MD_ / 128, B_ / 128), 256, MG_SMEM>>>(
        p_atth, p_attl, p_memh, p_meml, p_read, nullptr, M_, MD_);

    // cand (tanh), preds
    mgemm_kernel<2><<<dim3(MD_ / 128, B_ / 128), 256, MG_SMEM>>>(
        p_hidh, p_hidl, p_wwh, p_wwl, p_cand, write_b, U_, MD_);
    mgemm_kernel<0><<<dim3(O_ / 128, B_ / 128), 256, MG_SMEM>>>(
        p_hidh, p_hidl, p_owh, p_owl, p_preds, out_b, U_, O_);

    // memory update
    colmean_kernel<<<(M_ + 255) / 256, 256>>>(p_att, p_cma, M_);
    colmean_kernel<<<(MD_ + 255) / 256, 256>>>(p_cand, p_cmc, MD_);
    newmem_kernel<<<(M_ * MD_ + 255) / 256, 256>>>(mem, upgate, out + (size_t)B_ * O_);

    // critic (tiny, FFMA path)
    sgemm_kernel<1><<<dim3(1, B_ / 64), 256>>>(p_read,  cw1, p_feat + 0,  cb1, B_, 32, MD_, MD_, 32, 96);
    sgemm_kernel<1><<<dim3(1, B_ / 64), 256>>>(p_preds, cw2, p_feat + 32, cb2, B_, 32, O_,  O_,  32, 96);
    sgemm_kernel<1><<<dim3(1, B_ / 64), 256>>>(p_hidden,cw3, p_feat + 64, cb3, B_, 32, U_,  U_,  32, 96);
    sgemm_kernel<1><<<dim3(1, B_ / 64), 256>>>(p_feat,  cw4, p_fused,     cb4, B_, 64, 96,  96,  64, 64);

    final_kernel<<<B_, 128>>>(cw5, cb5, thr, out);
}

// round 6
// speedup vs baseline: 2.1538x; 1.2448x over previous
#include <cuda_runtime.h>
#include <cuda_bf16.h>
#include <cstdint>
#include <math.h>

// ---------------- problem dims ----------------
#define B_   1024
#define D_   1024
#define U_   2048
#define NB   4
#define M_   2048
#define MD_  1024
#define O_   512
#define KX   (D_*NB)   // 4096
#define NW   3584      // fused weight rows: att(2048) + write(1024) + out(512)

// ---------------- device scratch (allocation-free) ----------------
__device__ __nv_bfloat16 d_xgh[B_ * KX],  d_xgl[B_ * KX];     // A of hidden GEMM
__device__ __nv_bfloat16 d_w2h[U_ * KX],  d_w2l[U_ * KX];     // B of hidden GEMM [U][KX]
__device__ __nv_bfloat16 d_bwh[NW * U_],  d_bwl[NW * U_];     // fused [att_w^T; write_w^T; out_w^T]
__device__ __nv_bfloat16 d_memh[MD_ * M_], d_meml[MD_ * M_];  // mem^T [MD][M]
__device__ float d_gate[B_ * NB];
__device__ float d_hidden[B_ * U_];
__device__ __nv_bfloat16 d_hidh[B_ * U_], d_hidl[B_ * U_];
__device__ float d_att[B_ * M_];
__device__ __nv_bfloat16 d_atth[B_ * M_], d_attl[B_ * M_];
__device__ float d_read[B_ * MD_];
__device__ float d_cand[B_ * MD_];
__device__ float d_preds[B_ * O_];
__device__ float d_feat[B_ * 96];
__device__ float d_fused[B_ * 64];
__device__ float d_cma[M_];
__device__ float d_cmc[MD_];
__device__ float d_actw[9];

// ---------------- bf16 hi/lo split ----------------
__device__ __forceinline__ void split2(float v, __nv_bfloat16& h, __nv_bfloat16& l) {
    h = __float2bfloat16(v);
    l = __float2bfloat16(v - __bfloat162float(h));
}

// ---------------- low-level helpers ----------------
__device__ __forceinline__ uint32_t smem_to_u32(const void* smem_ptr) {
    uint32_t addr;
    asm("{ .reg .u64 tmp; cvta.to.shared.u64 tmp, %1; cvt.u32.u64 %0, tmp; }"
        : "=r"(addr) : "l"(smem_ptr));
    return addr;
}
__device__ __forceinline__ void cp16(uint32_t dst, const void* src) {
    asm volatile("cp.async.cg.shared.global [%0], [%1], 16;" :: "r"(dst), "l"(src));
}
__device__ __forceinline__ void ldsm4(uint32_t* r, uint32_t addr) {
    asm volatile("ldmatrix.sync.aligned.m8n8.x4.shared.b16 {%0,%1,%2,%3}, [%4];"
        : "=r"(r[0]), "=r"(r[1]), "=r"(r[2]), "=r"(r[3]) : "r"(addr));
}
__device__ __forceinline__ void mma16816(float* c, const uint32_t* a, const uint32_t* b) {
    asm volatile(
        "mma.sync.aligned.m16n8k16.row.col.f32.bf16.bf16.f32 "
        "{%0,%1,%2,%3}, {%4,%5,%6,%7}, {%8,%9}, {%0,%1,%2,%3};"
        : "+f"(c[0]), "+f"(c[1]), "+f"(c[2]), "+f"(c[3])
        : "r"(a[0]), "r"(a[1]), "r"(a[2]), "r"(a[3]), "r"(b[0]), "r"(b[1]));
}

// ======================= bf16-split MMA GEMM =======================
// C = (Ah+Al) @ (Bh+Bl)^T via Ah*Bh + Ah*Bl + Al*Bh, fp32 accum.
// CTA tile 128x128, BK=32, 256 threads (8 warps as 2x4, each warp 64x32).
// MODE 0: single output C0 (ld N0, bias b0, no act)
// MODE 1: merged 3-output dispatch on bn: [0,2048)->C0/b0/ld2048,
//         [2048,3072)->C1/b1/ld1024 + tanh, [3072,3584)->C2/b2/ld512
#define MG_STRIDE 80
#define MG_TILE   (128 * MG_STRIDE)          // 10240 B
#define MG_STAGE  (4 * MG_TILE)              // 40960 B (Ah, Al, Bh, Bl)
#define MG_STAGES 4
#define MG_SMEM   (MG_STAGES * MG_STAGE)     // 163840 B

template<int MODE>
__global__ void __launch_bounds__(256, 1) mgemm_kernel(
    const __nv_bfloat16* __restrict__ Ah, const __nv_bfloat16* __restrict__ Al,
    const __nv_bfloat16* __restrict__ Bh, const __nv_bfloat16* __restrict__ Bl,
    float* __restrict__ C0, float* __restrict__ C1, float* __restrict__ C2,
    const float* __restrict__ b0, const float* __restrict__ b1, const float* __restrict__ b2,
    int K, int N0)
{
    extern __shared__ char smem[];
    uint32_t sbase = smem_to_u32(smem);
    int tid = threadIdx.x, wid = tid >> 5, lane = tid & 31;
    int bm = blockIdx.y << 7, bn = blockIdx.x << 7;
    int wm = wid >> 2, wn = wid & 3;             // warp tile (64 x 32)
    int qrow = lane >> 2, qcol = (lane & 3) << 1;

    const __nv_bfloat16* gAh = Ah + (size_t)bm * K;
    const __nv_bfloat16* gAl = Al + (size_t)bm * K;
    const __nv_bfloat16* gBh = Bh + (size_t)bn * K;
    const __nv_bfloat16* gBl = Bl + (size_t)bn * K;

    int row0 = tid >> 2, seg0 = tid & 3;                 // idx = tid
    int row1 = (tid + 256) >> 2, seg1 = tid & 3;         // idx = tid + 256
    uint32_t doff0 = row0 * MG_STRIDE + seg0 * 16;
    uint32_t doff1 = row1 * MG_STRIDE + seg1 * 16;

    uint32_t a_off = (wm * 64 + (lane & 15)) * MG_STRIDE + (lane >> 4) * 16;
    uint32_t b_off = (wn * 32 + (lane & 7) + ((lane >> 4) & 1) * 8) * MG_STRIDE
                   + ((lane >> 3) & 1) * 16;

    int nch = K >> 5;

#define LOAD_CHUNK(c, s) do {                                              \
    uint32_t st_ = sbase + (s) * MG_STAGE;                                 \
    size_t g0_ = (size_t)row0 * K + (c) * 32 + seg0 * 8;                   \
    size_t g1_ = (size_t)row1 * K + (c) * 32 + seg1 * 8;                   \
    cp16(st_ + 0*MG_TILE + doff0, gAh + g0_);                              \
    cp16(st_ + 0*MG_TILE + doff1, gAh + g1_);                              \
    cp16(st_ + 1*MG_TILE + doff0, gAl + g0_);                              \
    cp16(st_ + 1*MG_TILE + doff1, gAl + g1_);                              \
    cp16(st_ + 2*MG_TILE + doff0, gBh + g0_);                              \
    cp16(st_ + 2*MG_TILE + doff1, gBh + g1_);                              \
    cp16(st_ + 3*MG_TILE + doff0, gBl + g0_);                              \
    cp16(st_ + 3*MG_TILE + doff1, gBl + g1_);                              \
    asm volatile("cp.async.commit_group;" ::: "memory");                   \
} while (0)

    int pre = nch < MG_STAGES ? nch : MG_STAGES;
    for (int c = 0; c < pre; c++) LOAD_CHUNK(c, c);

    float acc[4][4][4];
#pragma unroll
    for (int i = 0; i < 4; i++)
#pragma unroll
        for (int j = 0; j < 4; j++)
#pragma unroll
            for (int r = 0; r < 4; r++) acc[i][j][r] = 0.0f;

    for (int c = 0; c < nch; c++) {
        {   // wait until chunk c resident: allowed pending = min(S-1, nch-c-1)
            int kw = nch - c - 1; if (kw > MG_STAGES - 1) kw = MG_STAGES - 1;
            if (kw >= 3)      asm volatile("cp.async.wait_group 3;" ::: "memory");
            else if (kw == 2) asm volatile("cp.async.wait_group 2;" ::: "memory");
            else if (kw == 1) asm volatile("cp.async.wait_group 1;" ::: "memory");
            else              asm volatile("cp.async.wait_group 0;" ::: "memory");
        }
        __syncthreads();

        uint32_t st = sbase + (c % MG_STAGES) * MG_STAGE;
#pragma unroll
        for (int ks = 0; ks < 2; ks++) {
            uint32_t kb = ks * 32;   // k16-step byte offset
            uint32_t aH[4][4], aL[4][4], bH[2][4], bL[2][4];
#pragma unroll
            for (int mi = 0; mi < 4; mi++) {
                uint32_t p = st + a_off + mi * 16 * MG_STRIDE + kb;
                ldsm4(aH[mi], p);
                ldsm4(aL[mi], p + MG_TILE);
            }
#pragma unroll
            for (int njp = 0; njp < 2; njp++) {
                uint32_t p = st + 2 * MG_TILE + b_off + njp * 16 * MG_STRIDE + kb;
                ldsm4(bH[njp], p);
                ldsm4(bL[njp], p + MG_TILE);
            }
#pragma unroll
            for (int mi = 0; mi < 4; mi++)
#pragma unroll
                for (int njp = 0; njp < 2; njp++)
#pragma unroll
                    for (int sub = 0; sub < 2; sub++) {
                        float* a_ = acc[mi][njp * 2 + sub];
                        mma16816(a_, aH[mi], &bH[njp][sub * 2]);
                        mma16816(a_, aH[mi], &bL[njp][sub * 2]);
                        mma16816(a_, aL[mi], &bH[njp][sub * 2]);
                    }
        }
        __syncthreads();
        if (c + MG_STAGES < nch) LOAD_CHUNK(c + MG_STAGES, (c + MG_STAGES) % MG_STAGES);
    }
#undef LOAD_CHUNK

    // epilogue: pick output / bias / ldc / act per mode
    float* Cp; const float* bp; int ldc, cb; bool dt = false;
    if (MODE == 0) {
        Cp = C0; bp = b0; ldc = N0; cb = bn;
    } else {
        if (bn < 2048)      { Cp = C0; bp = b0; ldc = M_;  cb = bn;        }
        else if (bn < 3072) { Cp = C1; bp = b1; ldc = MD_; cb = bn - 2048; dt = true; }
        else                { Cp = C2; bp = b2; ldc = O_;  cb = bn - 3072; }
    }
#pragma unroll
    for (int mi = 0; mi < 4; mi++) {
        int row = bm + wm * 64 + mi * 16 + qrow;
#pragma unroll
        for (int nj = 0; nj < 4; nj++) {
            int col = cb + wn * 32 + nj * 8 + qcol;
            float bb0 = 0.f, bb1 = 0.f;
            if (bp) { bb0 = bp[col]; bb1 = bp[col + 1]; }
            float2 v0 = make_float2(acc[mi][nj][0] + bb0, acc[mi][nj][1] + bb1);
            float2 v1 = make_float2(acc[mi][nj][2] + bb0, acc[mi][nj][3] + bb1);
            if (MODE == 1 && dt) {
                v0.x = tanhf(v0.x); v0.y = tanhf(v0.y);
                v1.x = tanhf(v1.x); v1.y = tanhf(v1.y);
            }
            *(float2*)(Cp + (size_t)row * ldc + col) = v0;
            *(float2*)(Cp + (size_t)(row + 8) * ldc + col) = v1;
        }
    }
}

// ======================= FFMA sgemm (shared body) =======================
__device__ __forceinline__ unsigned long long pk2(float lo, float hi) {
    unsigned long long r;
    asm("mov.b64 %0, {%1, %2};" : "=l"(r) : "f"(lo), "f"(hi));
    return r;
}
__device__ __forceinline__ void fma2(unsigned long long& c, unsigned long long a, unsigned long long b) {
    asm("fma.rn.f32x2 %0, %1, %2, %0;" : "+l"(c) : "l"(a), "l"(b));
}
__device__ __forceinline__ float2 upk2(unsigned long long v) {
    float2 r;
    asm("mov.b64 {%0, %1}, %2;" : "=f"(r.x), "=f"(r.y) : "l"(v));
    return r;
}

template<int ACT>   // 0=none, 1=relu
__device__ __forceinline__ void sgemm_body(
    const float* __restrict__ A, const float* __restrict__ Bm,
    float* __restrict__ C, const float* __restrict__ bias,
    int N, int K, int lda, int ldb, int ldc, int bm, int bn)
{
    __shared__ float As[16][64];
    __shared__ float Bs[16][64];
    int tid = threadIdx.x;
    int tx = tid & 15, ty = tid >> 4;

    int am = tid >> 2, ac = (tid & 3) * 4;
    int bk = tid >> 4, bnc = (tid & 15) * 4;
    bool bok = (bn + bnc) < N;

    unsigned long long acc[4][2];
#pragma unroll
    for (int i = 0; i < 4; i++) { acc[i][0] = 0ull; acc[i][1] = 0ull; }

    const float* Aptr = A + (size_t)(bm + am) * lda + ac;
    const float* Bptr = Bm + (size_t)bk * ldb + bn + bnc;

    for (int k0 = 0; k0 < K; k0 += 16) {
        float4 av = *(const float4*)(Aptr + k0);
        float4 bv = bok ? *(const float4*)(Bptr + (size_t)k0 * ldb)
                        : make_float4(0.f, 0.f, 0.f, 0.f);
        As[ac + 0][am] = av.x; As[ac + 1][am] = av.y;
        As[ac + 2][am] = av.z; As[ac + 3][am] = av.w;
        *(float4*)&Bs[bk][bnc] = bv;
        __syncthreads();
#pragma unroll
        for (int kk = 0; kk < 16; kk++) {
            float4 a = *(const float4*)&As[kk][ty * 4];
            float4 b = *(const float4*)&Bs[kk][tx * 4];
            unsigned long long bp0 = pk2(b.x, b.y), bp1 = pk2(b.z, b.w);
            unsigned long long a0 = pk2(a.x, a.x), a1 = pk2(a.y, a.y);
            unsigned long long a2 = pk2(a.z, a.z), a3 = pk2(a.w, a.w);
            fma2(acc[0][0], a0, bp0); fma2(acc[0][1], a0, bp1);
            fma2(acc[1][0], a1, bp0); fma2(acc[1][1], a1, bp1);
            fma2(acc[2][0], a2, bp0); fma2(acc[2][1], a2, bp1);
            fma2(acc[3][0], a3, bp0); fma2(acc[3][1], a3, bp1);
        }
        __syncthreads();
    }

    int col = bn + tx * 4;
    if (col < N) {
        float4 bb = make_float4(0.f, 0.f, 0.f, 0.f);
        if (bias) bb = *(const float4*)(bias + col);
#pragma unroll
        for (int i = 0; i < 4; i++) {
            int rrow = bm + ty * 4 + i;
            float2 v0 = upk2(acc[i][0]), v1 = upk2(acc[i][1]);
            float4 v = make_float4(v0.x + bb.x, v0.y + bb.y, v1.x + bb.z, v1.y + bb.w);
            if (ACT == 1) {
                v.x = fmaxf(v.x, 0.f); v.y = fmaxf(v.y, 0.f);
                v.z = fmaxf(v.z, 0.f); v.w = fmaxf(v.w, 0.f);
            }
            *(float4*)(C + (size_t)rrow * ldc + col) = v;
        }
    }
}

template<int ACT>
__global__ void __launch_bounds__(256) sgemm_kernel(
    const float* __restrict__ A, const float* __restrict__ Bm,
    float* __restrict__ C, const float* __restrict__ bias,
    int N, int K, int lda, int ldb, int ldc)
{
    sgemm_body<ACT>(A, Bm, C, bias, N, K, lda, ldb, ldc,
                    blockIdx.y * 64, blockIdx.x * 64);
}

// fused critic feature GEMMs: z selects (read|preds|hidden) segment, all relu
__global__ void __launch_bounds__(256) critic3_kernel(
    const float* __restrict__ read, const float* __restrict__ preds,
    const float* __restrict__ hidden,
    const float* __restrict__ cw1, const float* __restrict__ cb1,
    const float* __restrict__ cw2, const float* __restrict__ cb2,
    const float* __restrict__ cw3, const float* __restrict__ cb3,
    float* __restrict__ feat)
{
    const float* A; const float* Bm; const float* bias; int K, foff;
    if (blockIdx.z == 0)      { A = read;   Bm = cw1; bias = cb1; K = MD_; foff = 0;  }
    else if (blockIdx.z == 1) { A = preds;  Bm = cw2; bias = cb2; K = O_;  foff = 32; }
    else                      { A = hidden; Bm = cw3; bias = cb3; K = U_;  foff = 64; }
    sgemm_body<1>(A, Bm, feat + foff, bias, 32, K, K, 32, 96, blockIdx.y * 64, 0);
}

// ======================= elementwise / small kernels =======================
// qact with a single expf: p = e^{-|x|} drives all 9 activations.
__device__ __forceinline__ float qact(float x, const float* w) {
    float ax = fabsf(x);
    float p  = expf(-ax);                 // e^{-|x|}
    float p2 = p * p;
    float r  = 1.0f / (1.0f + p);         // sigmoid(|x|)
    bool pos = x >= 0.0f;
    float sig = pos ? r : p * r;          // sigmoid(x)
    float em1 = p - 1.0f;                 // e^x - 1 for x<0 (p = e^x there)
    float elu = pos ? x : em1;
    float th  = (1.0f - p2) / (1.0f + p2);
    th = pos ? th : -th;                  // tanh(x)
    float relu = pos ? x : 0.0f;
    float silu = x * sig;
    float gelu = 0.5f * x * (1.0f + erff(x * 0.7071067811865475f));
    const float SELU_L = 1.0507009873554805f, SELU_A = 1.6732632423543772f;
    float selu = SELU_L * (pos ? x : SELU_A * em1);
    // mish: tanh(softplus(x)) with q = e^{-softplus(x)} = (pos ? p : 1) * r
    float q  = (pos ? p : 1.0f) * r;
    float q2 = q * q;
    float mish = x * (1.0f - q2) / (1.0f + q2);
    return w[0]*sig + w[1]*elu + w[2]*th + w[3]*relu + w[4]*silu
         + w[5]*gelu + w[6]*selu + w[7]*mish + w[8]*x;
}

__global__ void prep_actw_kernel(const float* __restrict__ aw) {
    if (threadIdx.x == 0) {
        float m = -1e30f;
        for (int i = 0; i < 9; i++) m = fmaxf(m, aw[i]);
        float e[9], s = 0.0f;
        for (int i = 0; i < 9; i++) { e[i] = expf(aw[i] - m); s += e[i]; }
        float inv = 1.0f / s;
        for (int i = 0; i < 9; i++) d_actw[i] = e[i] * inv;
    }
}

__global__ void gate_kernel(const float* __restrict__ x,
                            const float* __restrict__ gw,
                            const float* __restrict__ gb) {
    int b = blockIdx.x, t = threadIdx.x;   // 128 threads
    float4 s = make_float4(0.f, 0.f, 0.f, 0.f);
    for (int i = t; i < D_; i += 128) {
        float xv = x[(size_t)b * D_ + i];
        float4 g = *(const float4*)(gw + (size_t)i * 4);
        s.x += xv * g.x; s.y += xv * g.y; s.z += xv * g.z; s.w += xv * g.w;
    }
    __shared__ float4 red[128];
    red[t] = s; __syncthreads();
    for (int off = 64; off > 0; off >>= 1) {
        if (t < off) {
            red[t].x += red[t+off].x; red[t].y += red[t+off].y;
            red[t].z += red[t+off].z; red[t].w += red[t+off].w;
        }
        __syncthreads();
    }
    if (t == 0) {
        float l[4] = { red[0].x + gb[0], red[0].y + gb[1], red[0].z + gb[2], red[0].w + gb[3] };
        float m = fmaxf(fmaxf(l[0], l[1]), fmaxf(l[2], l[3]));
        float e[4], sum = 0.0f;
        for (int n = 0; n < 4; n++) { e[n] = expf(l[n] - m); sum += e[n]; }
        float inv = 1.0f / sum;
        for (int n = 0; n < 4; n++) d_gate[b * 4 + n] = e[n] * inv;
    }
}

// xg[b, i*4+n] = x[b,i]*gate[b,n]  -> bf16 hi/lo
__global__ void xg_split_kernel(const float* __restrict__ x) {
    int idx = blockIdx.x * blockDim.x + threadIdx.x;
    if (idx >= B_ * D_) return;
    int b = idx >> 10, i = idx & 1023;
    float xv = x[idx];
    float4 g = *(const float4*)(d_gate + b * 4);
    float v[4] = { xv * g.x, xv * g.y, xv * g.z, xv * g.w };
    __nv_bfloat16 h[4], l[4];
#pragma unroll
    for (int n = 0; n < 4; n++) split2(v[n], h[n], l[n]);
    size_t o = (size_t)b * KX + i * 4;
    __nv_bfloat162 t0, t1;
    t0.x = h[0]; t0.y = h[1]; t1.x = h[2]; t1.y = h[3];
    ((__nv_bfloat162*)(d_xgh + o))[0] = t0;
    ((__nv_bfloat162*)(d_xgh + o))[1] = t1;
    t0.x = l[0]; t0.y = l[1]; t1.x = l[2]; t1.y = l[3];
    ((__nv_bfloat162*)(d_xgl + o))[0] = t0;
    ((__nv_bfloat162*)(d_xgl + o))[1] = t1;
}

// w2T[u][i*4+n] = w[i,u,n]  -> bf16 hi/lo, via smem transpose
__global__ void w2t_split_kernel(const float* __restrict__ w) {
    __shared__ float4 s[32][33];
    int u0 = blockIdx.x << 5, i0 = blockIdx.y << 5;
    int tx = threadIdx.x & 31, ty = threadIdx.x >> 5;
    const float4* w4 = (const float4*)w;
    for (int r = ty; r < 32; r += 8)
        s[r][tx] = w4[(size_t)(i0 + r) * U_ + u0 + tx];
    __syncthreads();
    for (int r = ty; r < 32; r += 8) {
        float4 v = s[tx][r];   // i = i0+tx, u = u0+r
        __nv_bfloat16 h[4], l[4];
        split2(v.x, h[0], l[0]); split2(v.y, h[1], l[1]);
        split2(v.z, h[2], l[2]); split2(v.w, h[3], l[3]);
        size_t o = (size_t)(u0 + r) * KX + (i0 + tx) * 4;
        __nv_bfloat162 t0, t1;
        t0.x = h[0]; t0.y = h[1]; t1.x = h[2]; t1.y = h[3];
        ((__nv_bfloat162*)(d_w2h + o))[0] = t0;
        ((__nv_bfloat162*)(d_w2h + o))[1] = t1;
        t0.x = l[0]; t0.y = l[1]; t1.x = l[2]; t1.y = l[3];
        ((__nv_bfloat162*)(d_w2l + o))[0] = t0;
        ((__nv_bfloat162*)(d_w2l + o))[1] = t1;
    }
}

// generic transpose+split: src fp32 [K][N] -> dst bf16 hi/lo [N][K]
__global__ void tsplit_kernel(const float* __restrict__ src,
                              __nv_bfloat16* __restrict__ dh, __nv_bfloat16* __restrict__ dl,
                              int K, int N) {
    __shared__ float s[32][33];
    int n0 = blockIdx.x << 5, k0 = blockIdx.y << 5;
    int tx = threadIdx.x & 31, ty = threadIdx.x >> 5;
    for (int r = ty; r < 32; r += 8)
        s[r][tx] = src[(size_t)(k0 + r) * N + n0 + tx];
    __syncthreads();
    for (int r = ty; r < 32; r += 8) {
        float v = s[tx][r];   // k = k0+tx, n = n0+r
        __nv_bfloat16 h, l;
        split2(v, h, l);
        size_t o = (size_t)(n0 + r) * K + k0 + tx;
        dh[o] = h; dl[o] = l;
    }
}

// hidden = qact(pre + gate·b) * mask ; also bf16 hi/lo
__global__ void hidden_act_split_kernel(const float* __restrict__ bvec,
                                        const float* __restrict__ mask) {
    int idx = blockIdx.x * blockDim.x + threadIdx.x;
    if (idx >= B_ * U_) return;
    int b = idx >> 11, u = idx & 2047;
    float4 g  = *(const float4*)(d_gate + b * 4);
    float4 bb = *(const float4*)(bvec + (size_t)u * 4);
    float bias = g.x * bb.x + g.y * bb.y + g.z * bb.z + g.w * bb.w;
    float w[9];
#pragma unroll
    for (int i = 0; i < 9; i++) w[i] = d_actw[i];
    float hv = qact(d_hidden[idx] + bias, w) * mask[u];
    d_hidden[idx] = hv;
    __nv_bfloat16 h, l;
    split2(hv, h, l);
    d_hidh[idx] = h; d_hidl[idx] = l;
}

// row softmax in place + bf16 hi/lo
__global__ void softmax_split_kernel(float* __restrict__ data,
                                     __nv_bfloat16* __restrict__ oh,
                                     __nv_bfloat16* __restrict__ ol, int ncol) {
    size_t base = (size_t)blockIdx.x * ncol;
    float* row = data + base;
    int t = threadIdx.x;   // 256
    __shared__ float red[256];
    float m = -1e30f;
    for (int i = t; i < ncol; i += 256) m = fmaxf(m, row[i]);
    red[t] = m; __syncthreads();
    for (int off = 128; off > 0; off >>= 1) {
        if (t < off) red[t] = fmaxf(red[t], red[t + off]);
        __syncthreads();
    }
    m = red[0]; __syncthreads();
    float s = 0.0f;
    for (int i = t; i < ncol; i += 256) {
        float e = expf(row[i] - m);
        row[i] = e; s += e;
    }
    red[t] = s; __syncthreads();
    for (int off = 128; off > 0; off >>= 1) {
        if (t < off) red[t] += red[t + off];
        __syncthreads();
    }
    float inv = 1.0f / red[0];
    for (int i = t; i < ncol; i += 256) {
        float v = row[i] * inv;
        row[i] = v;
        __nv_bfloat16 h, l;
        split2(v, h, l);
        oh[base + i] = h; ol[base + i] = l;
    }
}

__global__ void colmean_kernel(const float* __restrict__ src, float* __restrict__ dst, int ncol) {
    int c = blockIdx.x * blockDim.x + threadIdx.x;
    if (c >= ncol) return;
    float s0 = 0.f, s1 = 0.f, s2 = 0.f, s3 = 0.f;
    for (int b = 0; b < B_; b += 4) {
        s0 += src[(size_t)(b + 0) * ncol + c];
        s1 += src[(size_t)(b + 1) * ncol + c];
        s2 += src[(size_t)(b + 2) * ncol + c];
        s3 += src[(size_t)(b + 3) * ncol + c];
    }
    dst[c] = (s0 + s1 + s2 + s3) * (1.0f / B_);
}

__global__ void newmem_kernel(const float* __restrict__ mem,
                              const float* __restrict__ ug,
                              float* __restrict__ outmem) {
    int idx = blockIdx.x * blockDim.x + threadIdx.x;
    if (idx >= M_ * MD_) return;
    int m = idx >> 10, d = idx & 1023;
    float u = d_cma[m] * ug[m];
    outmem[idx] = mem[idx] * (1.0f - u) + u * d_cmc[d];
}

__global__ void final_kernel(const float* __restrict__ cw5,
                             const float* __restrict__ cb5,
                             const float* __restrict__ thr,
                             float* __restrict__ out) {
    int b = blockIdx.x, t = threadIdx.x;   // 128 threads
    __shared__ float red[64];
    __shared__ float gsh;
    if (t < 64) red[t] = d_fused[b * 64 + t] * cw5[t * 2];
    __syncthreads();
    for (int off = 32; off > 0; off >>= 1) {
        if (t < off) red[t] += red[t + off];
        __syncthreads();
    }
    if (t == 0) {
        float o = red[0] + cb5[0];
        gsh = 1.0f / (1.0f + expf(-(o - thr[0])));
    }
    __syncthreads();
    float g = gsh;
    for (int j = t; j < O_; j += 128)
        out[(size_t)b * O_ + j] = d_preds[(size_t)b * O_ + j] * g;
}

// ======================= launch =======================
extern "C" void kernel_launch(void* const* d_in, const int* in_sizes, int n_in,
                              void* d_out, int out_size) {
    const float* x      = (const float*)d_in[0];
    const float* w      = (const float*)d_in[1];
    const float* bvec   = (const float*)d_in[2];
    const float* gate_w = (const float*)d_in[3];
    const float* gate_b = (const float*)d_in[4];
    const float* act_w  = (const float*)d_in[5];
    const float* mask   = (const float*)d_in[6];
    const float* mem    = (const float*)d_in[7];
    const float* att_w  = (const float*)d_in[8];
    const float* att_b  = (const float*)d_in[9];
    const float* write_w= (const float*)d_in[10];
    const float* write_b= (const float*)d_in[11];
    const float* upgate = (const float*)d_in[12];
    const float* out_w  = (const float*)d_in[13];
    const float* out_b  = (const float*)d_in[14];
    const float* cw1 = (const float*)d_in[15]; const float* cb1 = (const float*)d_in[16];
    const float* cw2 = (const float*)d_in[17]; const float* cb2 = (const float*)d_in[18];
    const float* cw3 = (const float*)d_in[19]; const float* cb3 = (const float*)d_in[20];
    const float* cw4 = (const float*)d_in[21]; const float* cb4 = (const float*)d_in[22];
    const float* cw5 = (const float*)d_in[23]; const float* cb5 = (const float*)d_in[24];
    const float* thr = (const float*)d_in[25];
    float* out = (float*)d_out;

    __nv_bfloat16 *p_xgh, *p_xgl, *p_w2h, *p_w2l, *p_bwh, *p_bwl, *p_memh, *p_meml,
                  *p_hidh, *p_hidl, *p_atth, *p_attl;
    float *p_hidden, *p_att, *p_read, *p_cand, *p_preds, *p_feat, *p_fused, *p_cma, *p_cmc;
    cudaGetSymbolAddress((void**)&p_xgh, d_xgh);   cudaGetSymbolAddress((void**)&p_xgl, d_xgl);
    cudaGetSymbolAddress((void**)&p_w2h, d_w2h);   cudaGetSymbolAddress((void**)&p_w2l, d_w2l);
    cudaGetSymbolAddress((void**)&p_bwh, d_bwh);   cudaGetSymbolAddress((void**)&p_bwl, d_bwl);
    cudaGetSymbolAddress((void**)&p_memh, d_memh); cudaGetSymbolAddress((void**)&p_meml, d_meml);
    cudaGetSymbolAddress((void**)&p_hidh, d_hidh); cudaGetSymbolAddress((void**)&p_hidl, d_hidl);
    cudaGetSymbolAddress((void**)&p_atth, d_atth); cudaGetSymbolAddress((void**)&p_attl, d_attl);
    cudaGetSymbolAddress((void**)&p_hidden, d_hidden);
    cudaGetSymbolAddress((void**)&p_att, d_att);
    cudaGetSymbolAddress((void**)&p_read, d_read);
    cudaGetSymbolAddress((void**)&p_cand, d_cand);
    cudaGetSymbolAddress((void**)&p_preds, d_preds);
    cudaGetSymbolAddress((void**)&p_feat, d_feat);
    cudaGetSymbolAddress((void**)&p_fused, d_fused);
    cudaGetSymbolAddress((void**)&p_cma, d_cma);
    cudaGetSymbolAddress((void**)&p_cmc, d_cmc);

    cudaFuncSetAttribute(mgemm_kernel<0>, cudaFuncAttributeMaxDynamicSharedMemorySize, MG_SMEM);
    cudaFuncSetAttribute(mgemm_kernel<1>, cudaFuncAttributeMaxDynamicSharedMemorySize, MG_SMEM);

    // prep + operand conversion (ordered so mgemm<0> hidden is launch index 5 for ncu)
    prep_actw_kernel<<<1, 32>>>(act_w);                                   // 0
    gate_kernel<<<B_, 128>>>(x, gate_w, gate_b);                          // 1
    xg_split_kernel<<<(B_ * D_ + 255) / 256, 256>>>(x);                   // 2
    w2t_split_kernel<<<dim3(U_ / 32, D_ / 32), 256>>>(w);                 // 3
    tsplit_kernel<<<dim3(M_ / 32, U_ / 32), 256>>>(att_w, p_bwh, p_bwl, U_, M_);  // 4

    // hidden_pre = xg @ w2^T   (1024 x 2048, K=4096)  -- launch index 5
    mgemm_kernel<0><<<dim3(U_ / 128, B_ / 128), 256, MG_SMEM>>>(
        p_xgh, p_xgl, p_w2h, p_w2l,
        p_hidden, nullptr, nullptr, nullptr, nullptr, nullptr, KX, U_);

    // remaining weight conversions
    tsplit_kernel<<<dim3(MD_ / 32, U_ / 32), 256>>>(write_w, p_bwh + (size_t)2048 * U_,
                                                    p_bwl + (size_t)2048 * U_, U_, MD_);
    tsplit_kernel<<<dim3(O_ / 32, U_ / 32), 256>>>(out_w, p_bwh + (size_t)3072 * U_,
                                                   p_bwl + (size_t)3072 * U_, U_, O_);
    tsplit_kernel<<<dim3(MD_ / 32, M_ / 32), 256>>>(mem, p_memh, p_meml, M_, MD_);

    hidden_act_split_kernel<<<(B_ * U_ + 255) / 256, 256>>>(bvec, mask);

    // merged att-logits + cand(tanh) + preds GEMM  (1024 x 3584, K=2048)
    mgemm_kernel<1><<<dim3(NW / 128, B_ / 128), 256, MG_SMEM>>>(
        p_hidh, p_hidl, p_bwh, p_bwl,
        p_att, p_cand, p_preds, att_b, write_b, out_b, U_, 0);

    softmax_split_kernel<<<B_, 256>>>(p_att, p_atth, p_attl, M_);

    // read = att_softmax @ mem  (1024 x 1024, K=2048)
    mgemm_kernel<0><<<dim3(MD_ / 128, B_ / 128), 256, MG_SMEM>>>(
        p_atth, p_attl, p_memh, p_meml,
        p_read, nullptr, nullptr, nullptr, nullptr, nullptr, M_, MD_);

    // memory update
    colmean_kernel<<<(M_ + 255) / 256, 256>>>(p_att, p_cma, M_);
    colmean_kernel<<<(MD_ + 255) / 256, 256>>>(p_cand, p_cmc, MD_);
    newmem_kernel<<<(M_ * MD_ + 255) / 256, 256>>>(mem, upgate, out + (size_t)B_ * O_);

    // critic: fused 3 feature GEMMs, then fusion GEMM
    critic3_kernel<<<dim3(1, B_ / 64, 3), 256>>>(p_read, p_preds, p_hidden,
                                                 cw1, cb1, cw2, cb2, cw3, cb3, p_feat);
    sgemm_kernel<1><<<dim3(1, B_ / 64), 256>>>(p_feat, cw4, p_fused, cb4, 64, 96, 96, 64, 64);

    final_kernel<<<B_, 128>>>(cw5, cb5, thr, out);
}